// round 2
// baseline (speedup 1.0000x reference)
#include <cuda_runtime.h>
#include <math.h>

// Problem constants
#define TT     256
#define BB     64
#define INP    1024
#define HH     512
#define FOURH  2048
#define KP     1024        // K for projections (IN == 2H == 1024 for both layers)
#define MM     (TT*BB)     // 16384

// ---------------------------------------------------------------------------
// Device scratch (static allocation only — no cudaMalloc allowed)
// ---------------------------------------------------------------------------
__device__ float g_buf0[(size_t)TT*BB*2*HH];            // layer-0 output / layer-1 input (67MB)
__device__ float g_xproj[(size_t)2*MM*FOURH];           // per-direction input projections (268MB)
__device__ float g_h[2][2][BB*HH];                      // [dir][pingpong][b*H]
__device__ float g_c[2][BB*HH];                         // [dir][b*H]

// ---------------------------------------------------------------------------
// Zero h / c state at start of each layer
// ---------------------------------------------------------------------------
__global__ void zero_hc_kernel() {
    int i = blockIdx.x * blockDim.x + threadIdx.x;
    if (i < BB*HH) {
        g_h[0][0][i] = 0.f; g_h[0][1][i] = 0.f;
        g_h[1][0][i] = 0.f; g_h[1][1][i] = 0.f;
        g_c[0][i]    = 0.f; g_c[1][i]    = 0.f;
    }
}

// ---------------------------------------------------------------------------
// Input projection GEMM:  C[dir][m][n] = sum_k A[m][k] * W[dir][n][k] + b(n)
// A: [M=16384, K=1024] row-major;  W: [2][4H=2048][K] row-major (both K-major "NT")
// Tile: BM=128 x BN=64 x BK=32, 256 threads, 8x4 per-thread micro-tile.
// ---------------------------------------------------------------------------
#define BM 128
#define BN 64
#define BK 32

__global__ __launch_bounds__(256) void proj_kernel(
    const float* __restrict__ A,       // [MM, KP]
    const float* __restrict__ Wl,      // w_ih for this layer: [2][FOURH][KP]
    const float* __restrict__ b1l,     // b_ih for this layer: [2][FOURH]
    const float* __restrict__ b2l)     // b_hh for this layer: [2][FOURH]
{
    const int dir = blockIdx.z;
    const float* W  = Wl  + (size_t)dir * FOURH * KP;
    const float* b1 = b1l + (size_t)dir * FOURH;
    const float* b2 = b2l + (size_t)dir * FOURH;
    float* C = g_xproj + (size_t)dir * MM * FOURH;

    const int m0 = blockIdx.x * BM;
    const int n0 = blockIdx.y * BN;
    const int tid = threadIdx.x;
    const int tn = tid & 15;      // 0..15  (n dimension, 4 cols each)
    const int tm = tid >> 4;      // 0..15  (m dimension, 8 rows each)

    __shared__ float As[BK][BM + 4];   // transposed, padded (132 stride, 16B-aligned rows)
    __shared__ float Ws[BK][BN + 4];   // transposed, padded (68 stride)

    float acc[8][4];
#pragma unroll
    for (int i = 0; i < 8; i++)
#pragma unroll
        for (int j = 0; j < 4; j++) acc[i][j] = 0.f;

    for (int k0 = 0; k0 < KP; k0 += BK) {
        // Load A tile: 128 rows x 8 float4  (coalesced along k)
#pragma unroll
        for (int it = 0; it < 4; it++) {
            int i = it * 256 + tid;
            int row = i >> 3, kq = i & 7;
            float4 v = *(const float4*)&A[(size_t)(m0 + row) * KP + k0 + kq * 4];
            As[kq*4+0][row] = v.x; As[kq*4+1][row] = v.y;
            As[kq*4+2][row] = v.z; As[kq*4+3][row] = v.w;
        }
        // Load W tile: 64 rows x 8 float4
#pragma unroll
        for (int it = 0; it < 2; it++) {
            int i = it * 256 + tid;
            int row = i >> 3, kq = i & 7;
            float4 v = *(const float4*)&W[(size_t)(n0 + row) * KP + k0 + kq * 4];
            Ws[kq*4+0][row] = v.x; Ws[kq*4+1][row] = v.y;
            Ws[kq*4+2][row] = v.z; Ws[kq*4+3][row] = v.w;
        }
        __syncthreads();

#pragma unroll 8
        for (int kk = 0; kk < BK; kk++) {
            float4 a0 = *(const float4*)&As[kk][tm * 8];
            float4 a1 = *(const float4*)&As[kk][tm * 8 + 4];
            float4 bv = *(const float4*)&Ws[kk][tn * 4];
            float a[8] = {a0.x, a0.y, a0.z, a0.w, a1.x, a1.y, a1.z, a1.w};
            float b[4] = {bv.x, bv.y, bv.z, bv.w};
#pragma unroll
            for (int i = 0; i < 8; i++)
#pragma unroll
                for (int j = 0; j < 4; j++) acc[i][j] += a[i] * b[j];
        }
        __syncthreads();
    }

    // Epilogue: add bias, vector store
    float bs[4];
#pragma unroll
    for (int j = 0; j < 4; j++) {
        int n = n0 + tn * 4 + j;
        bs[j] = b1[n] + b2[n];
    }
#pragma unroll
    for (int i = 0; i < 8; i++) {
        int m = m0 + tm * 8 + i;
        float4 r;
        r.x = acc[i][0] + bs[0];
        r.y = acc[i][1] + bs[1];
        r.z = acc[i][2] + bs[2];
        r.w = acc[i][3] + bs[3];
        *(float4*)&C[(size_t)m * FOURH + n0 + tn * 4] = r;
    }
}

// ---------------------------------------------------------------------------
// One recurrent time step (both directions fused via blockIdx.z).
// Block: 128 threads, covers b-tile of 32 (blockIdx.y) x h-tile of 16 (blockIdx.x).
// Thread: 4 batches x 1 h-index x 4 gates (16 accumulators), then LSTM cell.
// grid = (32, 2, 2) -> 128 blocks.
// ---------------------------------------------------------------------------
__device__ __forceinline__ float sigmoidf_(float x) { return 1.f / (1.f + expf(-x)); }

#define KC 64   // k-chunk

__global__ __launch_bounds__(128) void step_kernel(
    int t,
    const float* __restrict__ Whhl,   // w_hh for this layer: [2][FOURH][HH]
    const int*   __restrict__ mask,   // [BB, TT]
    float*       __restrict__ outp)   // [TT, BB, 2H]
{
    const int dir = blockIdx.z;
    const int tt  = dir ? (TT - 1 - t) : t;
    const int h0  = blockIdx.x * 16;
    const int b0  = blockIdx.y * 32;

    const float* W   = Whhl + (size_t)dir * FOURH * HH;
    const float* hin = g_h[dir][t & 1];
    float*       hout = g_h[dir][(t + 1) & 1];
    float*       c    = g_c[dir];
    const float* xp  = g_xproj + (size_t)dir * MM * FOURH + (size_t)tt * BB * FOURH;

    __shared__ float hs[KC][36];       // transposed h tile [k][b], padded stride 36 (16B aligned)
    __shared__ float ws[64][KC + 4];   // W rows (row-major) [row][k], stride 68

    const int tid = threadIdx.x;       // 128
    const int tx = tid & 7;            // b-group (x4)
    const int ty = tid >> 3;           // h within tile (0..15)
    const int hidx = h0 + ty;

    float acc[4][4];                   // [gate][b]
#pragma unroll
    for (int g = 0; g < 4; g++)
#pragma unroll
        for (int i = 0; i < 4; i++) acc[g][i] = 0.f;

    for (int kc = 0; kc < HH; kc += KC) {
        // h tile: 32 b x 64 k = 512 float4; coalesced global loads, transpose into smem
#pragma unroll
        for (int it = 0; it < 4; it++) {
            int i = it * 128 + tid;
            int bl = i >> 4, kq = i & 15;
            float4 v = *(const float4*)&hin[(size_t)(b0 + bl) * HH + kc + kq * 4];
            hs[kq*4+0][bl] = v.x; hs[kq*4+1][bl] = v.y;
            hs[kq*4+2][bl] = v.z; hs[kq*4+3][bl] = v.w;
        }
        // W tile: 64 rows (16 h x 4 gates) x 64 k, row-major (no transpose)
#pragma unroll
        for (int it = 0; it < 8; it++) {
            int i = it * 128 + tid;
            int r = i >> 4, kq = i & 15;
            int g = r >> 4, hr = r & 15;
            float4 v = *(const float4*)&W[(size_t)(g * HH + h0 + hr) * HH + kc + kq * 4];
            *(float4*)&ws[r][kq * 4] = v;
        }
        __syncthreads();

#pragma unroll 16
        for (int kk = 0; kk < KC; kk++) {
            float4 hv = *(const float4*)&hs[kk][tx * 4];
            float w0 = ws[ty][kk];
            float w1 = ws[16 + ty][kk];
            float w2 = ws[32 + ty][kk];
            float w3 = ws[48 + ty][kk];
            acc[0][0] += w0 * hv.x; acc[0][1] += w0 * hv.y; acc[0][2] += w0 * hv.z; acc[0][3] += w0 * hv.w;
            acc[1][0] += w1 * hv.x; acc[1][1] += w1 * hv.y; acc[1][2] += w1 * hv.z; acc[1][3] += w1 * hv.w;
            acc[2][0] += w2 * hv.x; acc[2][1] += w2 * hv.y; acc[2][2] += w2 * hv.z; acc[2][3] += w2 * hv.w;
            acc[3][0] += w3 * hv.x; acc[3][1] += w3 * hv.y; acc[3][2] += w3 * hv.z; acc[3][3] += w3 * hv.w;
        }
        __syncthreads();
    }

    // LSTM cell epilogue
#pragma unroll
    for (int i = 0; i < 4; i++) {
        int b = b0 + tx * 4 + i;
        const float* xpb = xp + (size_t)b * FOURH;
        float gi = acc[0][i] + xpb[0 * HH + hidx];
        float gf = acc[1][i] + xpb[1 * HH + hidx];
        float gg = acc[2][i] + xpb[2 * HH + hidx];
        float go = acc[3][i] + xpb[3 * HH + hidx];

        float cold = c[(size_t)b * HH + hidx];
        float cn = sigmoidf_(gf) * cold + sigmoidf_(gi) * tanhf(gg);
        float hn = sigmoidf_(go) * tanhf(cn);

        float m = (float)mask[b * TT + tt];
        hn *= m; cn *= m;

        c[(size_t)b * HH + hidx]    = cn;
        hout[(size_t)b * HH + hidx] = hn;
        outp[((size_t)tt * BB + b) * (2 * HH) + dir * HH + hidx] = hn;
    }
}

// ---------------------------------------------------------------------------
// kernel_launch: 2 layers x (proj GEMM + state init + 256 steps)
// ---------------------------------------------------------------------------
extern "C" void kernel_launch(void* const* d_in, const int* in_sizes, int n_in,
                              void* d_out, int out_size)
{
    const float* x    = (const float*)d_in[0];
    const int*   mask = (const int*)  d_in[1];
    const float* w_ih = (const float*)d_in[2];   // [2][2][4H][IN]
    const float* w_hh = (const float*)d_in[3];   // [2][2][4H][H]
    const float* b_ih = (const float*)d_in[4];   // [2][2][4H]
    const float* b_hh = (const float*)d_in[5];   // [2][2][4H]
    float* out = (float*)d_out;

    float* buf0 = nullptr;
    cudaGetSymbolAddress((void**)&buf0, g_buf0);

    dim3 gproj(MM / BM, FOURH / BN, 2);   // 128 x 32 x 2
    dim3 gstep(HH / 16, BB / 32, 2);      // 32 x 2 x 2

    for (int layer = 0; layer < 2; layer++) {
        const float* inp  = (layer == 0) ? x : buf0;
        float*       outl = (layer == 1) ? out : buf0;

        proj_kernel<<<gproj, 256>>>(
            inp,
            w_ih + (size_t)layer * 2 * FOURH * KP,
            b_ih + (size_t)layer * 2 * FOURH,
            b_hh + (size_t)layer * 2 * FOURH);

        zero_hc_kernel<<<(BB*HH + 255) / 256, 256>>>();

        const float* whhl = w_hh + (size_t)layer * 2 * FOURH * HH;
        for (int t = 0; t < TT; t++) {
            step_kernel<<<gstep, 128>>>(t, whhl, mask, outl);
        }
    }
}

// round 3
// speedup vs baseline: 1.4624x; 1.4624x over previous
#include <cuda_runtime.h>
#include <math.h>
#include <stdint.h>

// Problem constants
#define TT     256
#define BB     64
#define HH     512
#define FOURH  2048
#define KP     1024
#define MM     (TT*BB)     // 16384

// ---------------------------------------------------------------------------
// Device scratch (static only — no cudaMalloc allowed)
// ---------------------------------------------------------------------------
__device__ float g_buf0[(size_t)MM*2*HH];            // layer-0 out / layer-1 in
__device__ float g_xproj[(size_t)2*MM*FOURH];        // input projections per dir
__device__ float g_h[2][2][HH*BB];                   // [dir][pingpong][h*64+b]  (TRANSPOSED)
__device__ float g_c[2][HH*BB];                      // [dir][h*64+b]
__device__ unsigned g_gbar[2];                       // per-dir step barrier counter

// ---------------------------------------------------------------------------
// PTX helpers
// ---------------------------------------------------------------------------
__device__ __forceinline__ uint32_t smem_u32(const void* p) {
    uint32_t a;
    asm("{ .reg .u64 t; cvta.to.shared.u64 t, %1; cvt.u32.u64 %0, t; }" : "=r"(a) : "l"(p));
    return a;
}
__device__ __forceinline__ void mbar_init(uint32_t mb, uint32_t cnt) {
    asm volatile("mbarrier.init.shared.b64 [%0], %1;" :: "r"(mb), "r"(cnt) : "memory");
}
__device__ __forceinline__ void mbar_expect_tx(uint32_t mb, uint32_t bytes) {
    asm volatile("mbarrier.arrive.expect_tx.shared.b64 _, [%0], %1;" :: "r"(mb), "r"(bytes) : "memory");
}
__device__ __forceinline__ void bulk_g2s(uint32_t dst, const void* src, uint32_t bytes, uint32_t mb) {
    asm volatile("cp.async.bulk.shared::cta.global.mbarrier::complete_tx::bytes [%0], [%1], %2, [%3];"
                 :: "r"(dst), "l"(src), "r"(bytes), "r"(mb) : "memory");
}
__device__ __forceinline__ void mbar_wait(uint32_t mb, uint32_t parity) {
    uint32_t done;
    asm volatile("{\n\t.reg .pred p;\n\t"
        "mbarrier.try_wait.parity.acquire.cta.shared::cta.b64 p, [%1], %2;\n\t"
        "selp.b32 %0, 1, 0, p;\n\t}"
        : "=r"(done) : "r"(mb), "r"(parity) : "memory");
    while (!done) {
        asm volatile("{\n\t.reg .pred p;\n\t"
            "mbarrier.try_wait.parity.acquire.cta.shared::cta.b64 p, [%1], %2, 0x989680;\n\t"
            "selp.b32 %0, 1, 0, p;\n\t}"
            : "=r"(done) : "r"(mb), "r"(parity) : "memory");
    }
}

// ---------------------------------------------------------------------------
// Zero state + barrier counters before each layer
// ---------------------------------------------------------------------------
__global__ void zero_hc_kernel() {
    int i = blockIdx.x * blockDim.x + threadIdx.x;
    if (i < HH*BB) {
        g_h[0][0][i] = 0.f; g_h[0][1][i] = 0.f;
        g_h[1][0][i] = 0.f; g_h[1][1][i] = 0.f;
        g_c[0][i]    = 0.f; g_c[1][i]    = 0.f;
    }
    if (i < 2) g_gbar[i] = 0u;
}

// ---------------------------------------------------------------------------
// Input projection GEMM (unchanged from R2 — known correct)
// ---------------------------------------------------------------------------
#define BM 128
#define BN 64
#define BK 32

__global__ __launch_bounds__(256) void proj_kernel(
    const float* __restrict__ A, const float* __restrict__ Wl,
    const float* __restrict__ b1l, const float* __restrict__ b2l)
{
    const int dir = blockIdx.z;
    const float* W  = Wl  + (size_t)dir * FOURH * KP;
    const float* b1 = b1l + (size_t)dir * FOURH;
    const float* b2 = b2l + (size_t)dir * FOURH;
    float* C = g_xproj + (size_t)dir * MM * FOURH;

    const int m0 = blockIdx.x * BM;
    const int n0 = blockIdx.y * BN;
    const int tid = threadIdx.x;
    const int tn = tid & 15;
    const int tm = tid >> 4;

    __shared__ float As[BK][BM + 4];
    __shared__ float Ws[BK][BN + 4];

    float acc[8][4];
#pragma unroll
    for (int i = 0; i < 8; i++)
#pragma unroll
        for (int j = 0; j < 4; j++) acc[i][j] = 0.f;

    for (int k0 = 0; k0 < KP; k0 += BK) {
#pragma unroll
        for (int it = 0; it < 4; it++) {
            int i = it * 256 + tid;
            int row = i >> 3, kq = i & 7;
            float4 v = *(const float4*)&A[(size_t)(m0 + row) * KP + k0 + kq * 4];
            As[kq*4+0][row] = v.x; As[kq*4+1][row] = v.y;
            As[kq*4+2][row] = v.z; As[kq*4+3][row] = v.w;
        }
#pragma unroll
        for (int it = 0; it < 2; it++) {
            int i = it * 256 + tid;
            int row = i >> 3, kq = i & 7;
            float4 v = *(const float4*)&W[(size_t)(n0 + row) * KP + k0 + kq * 4];
            Ws[kq*4+0][row] = v.x; Ws[kq*4+1][row] = v.y;
            Ws[kq*4+2][row] = v.z; Ws[kq*4+3][row] = v.w;
        }
        __syncthreads();

#pragma unroll 8
        for (int kk = 0; kk < BK; kk++) {
            float4 a0 = *(const float4*)&As[kk][tm * 8];
            float4 a1 = *(const float4*)&As[kk][tm * 8 + 4];
            float4 bv = *(const float4*)&Ws[kk][tn * 4];
            float a[8] = {a0.x, a0.y, a0.z, a0.w, a1.x, a1.y, a1.z, a1.w};
            float b[4] = {bv.x, bv.y, bv.z, bv.w};
#pragma unroll
            for (int i = 0; i < 8; i++)
#pragma unroll
                for (int j = 0; j < 4; j++) acc[i][j] += a[i] * b[j];
        }
        __syncthreads();
    }

    float bs[4];
#pragma unroll
    for (int j = 0; j < 4; j++) {
        int n = n0 + tn * 4 + j;
        bs[j] = b1[n] + b2[n];
    }
#pragma unroll
    for (int i = 0; i < 8; i++) {
        int m = m0 + tm * 8 + i;
        float4 r;
        r.x = acc[i][0] + bs[0];
        r.y = acc[i][1] + bs[1];
        r.z = acc[i][2] + bs[2];
        r.w = acc[i][3] + bs[3];
        *(float4*)&C[(size_t)m * FOURH + n0 + tn * 4] = r;
    }
}

// ---------------------------------------------------------------------------
// Persistent recurrence kernel: one launch runs all 256 steps of one layer.
// grid = (64, 2): blockIdx.x = h-block (8 h values), blockIdx.y = dir.
// 128 threads: tx = tid&15 (batch group of 4), th = tid>>4 (h within block).
// W_hh slice (32 rows x 512) loaded to smem ONCE. h streamed per step via
// cp.async.bulk. Per-dir global barrier (monotonic counter) between steps.
// ---------------------------------------------------------------------------
#define WSTRIDE 2056                       // 4*512 + 8 pad (bank-shift per h)
#define SM_WS 0                            // float offsets
#define SM_HS 16448                        // 8*2056
#define SM_XS (SM_HS + HH*BB)              // 16448+32768 = 49216
#define SM_MS (SM_XS + 2048)               // 51264
#define SM_MBAR_BYTE ((SM_MS + 64) * 4)    // 205312
#define SMEM_BYTES (SM_MBAR_BYTE + 64)     // 205376

__device__ __forceinline__ float sig_(float x) {
    return __fdividef(1.f, 1.f + __expf(-x));
}

__global__ __launch_bounds__(128, 1) void lstm_persistent(
    const float* __restrict__ Whhl,   // [2][4H][H]
    const int*   __restrict__ mask,   // [B][T]
    float*       __restrict__ outp)   // [T][B][2H]
{
    extern __shared__ float sm[];
    float* ws = sm + SM_WS;
    float* hs = sm + SM_HS;
    float* xs = sm + SM_XS;
    int*   ms = (int*)(sm + SM_MS);
    const uint32_t smbase = smem_u32(sm);
    const uint32_t mbar0  = smbase + SM_MBAR_BYTE;

    const int dir = blockIdx.y;
    const int h0  = blockIdx.x * 8;
    const int tid = threadIdx.x;
    const int tx  = tid & 15;     // batch group (4 batches)
    const int th  = tid >> 4;     // h index within block (0..7)

    const float* W   = Whhl + (size_t)dir * FOURH * HH;
    const float* xpD = g_xproj + (size_t)dir * MM * FOURH;

    // Load W slice once: rows {g*512 + h0 + hh : g in 0..3, hh in 0..7}
    for (int i = tid; i < 4096; i += 128) {
        int row = i >> 7, q = i & 127;
        int g = row >> 3, hh = row & 7;
        float4 v = *(const float4*)&W[(size_t)(g * HH + h0 + hh) * HH + q * 4];
        *(float4*)&ws[hh * WSTRIDE + g * HH + q * 4] = v;
    }
    if (tid == 0) {
        for (int c = 0; c < 4; c++) mbar_init(mbar0 + c * 8, 1);
    }
    __syncthreads();

    unsigned* bar = &g_gbar[dir];
    const float* wrow = ws + th * WSTRIDE;

    for (int t = 0; t < TT; t++) {
        const int tt = dir ? (TT - 1 - t) : t;
        const float* hin  = g_h[dir][t & 1];
        float*       hout = g_h[dir][(t + 1) & 1];

        // Kick off 4 chunked bulk copies of full h [512][64] into smem
        if (tid == 0) {
            asm volatile("fence.proxy.async.shared::cta;" ::: "memory");
#pragma unroll
            for (int c = 0; c < 4; c++) {
                uint32_t mb = mbar0 + c * 8;
                mbar_expect_tx(mb, 32768u);
                bulk_g2s(smbase + (SM_HS + c * 8192) * 4, hin + c * 8192, 32768u, mb);
            }
        }

        // Stage xproj slice [4 gates][8 h][64 b] and mask while copies fly
        const float* xp = xpD + (size_t)tt * BB * FOURH;
        for (int i = tid; i < 512; i += 128) {
            int b = i >> 3, r = i & 7;
            int g = r >> 1, hq = r & 1;
            float4 v = *(const float4*)&xp[(size_t)b * FOURH + g * HH + h0 + hq * 4];
            xs[(g * 8 + hq * 4 + 0) * 64 + b] = v.x;
            xs[(g * 8 + hq * 4 + 1) * 64 + b] = v.y;
            xs[(g * 8 + hq * 4 + 2) * 64 + b] = v.z;
            xs[(g * 8 + hq * 4 + 3) * 64 + b] = v.w;
        }
        if (tid < 64) ms[tid] = mask[tid * TT + tt];

        // GEMM: acc[g][j] = sum_k W[g*H+h0+th][k] * h[k][b=tx*4+j]
        float4 a0 = {0,0,0,0}, a1 = {0,0,0,0}, a2 = {0,0,0,0}, a3 = {0,0,0,0};
        const uint32_t par = (uint32_t)(t & 1);
#pragma unroll
        for (int c = 0; c < 4; c++) {
            mbar_wait(mbar0 + c * 8, par);
            const float* hc = hs + c * 128 * 64;
            const float* wc = wrow + c * 128;
#pragma unroll 8
            for (int kk = 0; kk < 128; kk++) {
                float4 hv = *(const float4*)&hc[kk * 64 + tx * 4];
                float w0 = wc[kk];
                float w1 = wc[512 + kk];
                float w2 = wc[1024 + kk];
                float w3 = wc[1536 + kk];
                a0.x += w0 * hv.x; a0.y += w0 * hv.y; a0.z += w0 * hv.z; a0.w += w0 * hv.w;
                a1.x += w1 * hv.x; a1.y += w1 * hv.y; a1.z += w1 * hv.z; a1.w += w1 * hv.w;
                a2.x += w2 * hv.x; a2.y += w2 * hv.y; a2.z += w2 * hv.z; a2.w += w2 * hv.w;
                a3.x += w3 * hv.x; a3.y += w3 * hv.y; a3.z += w3 * hv.z; a3.w += w3 * hv.w;
            }
        }

        __syncthreads();   // xs staging complete before epilogue reads

        // LSTM cell epilogue (4 batches per thread, 1 h, all 4 gates)
        float4 xg0 = *(const float4*)&xs[(0 * 8 + th) * 64 + tx * 4];
        float4 xg1 = *(const float4*)&xs[(1 * 8 + th) * 64 + tx * 4];
        float4 xg2 = *(const float4*)&xs[(2 * 8 + th) * 64 + tx * 4];
        float4 xg3 = *(const float4*)&xs[(3 * 8 + th) * 64 + tx * 4];
        float* crow = &g_c[dir][(h0 + th) * 64];
        float4 cv = *(const float4*)&crow[tx * 4];

        float gi[4] = {a0.x + xg0.x, a0.y + xg0.y, a0.z + xg0.z, a0.w + xg0.w};
        float gf[4] = {a1.x + xg1.x, a1.y + xg1.y, a1.z + xg1.z, a1.w + xg1.w};
        float gg[4] = {a2.x + xg2.x, a2.y + xg2.y, a2.z + xg2.z, a2.w + xg2.w};
        float go[4] = {a3.x + xg3.x, a3.y + xg3.y, a3.z + xg3.z, a3.w + xg3.w};
        float co[4] = {cv.x, cv.y, cv.z, cv.w};

        float hn[4], cn[4];
#pragma unroll
        for (int j = 0; j < 4; j++) {
            float si = sig_(gi[j]);
            float sf = sig_(gf[j]);
            float so = sig_(go[j]);
            float tg = 2.f * sig_(2.f * gg[j]) - 1.f;   // tanh
            float c2 = sf * co[j] + si * tg;
            float tc = 2.f * sig_(2.f * c2) - 1.f;      // tanh
            float h2 = so * tc;
            float m  = (float)ms[tx * 4 + j];
            cn[j] = c2 * m;
            hn[j] = h2 * m;
        }

        *(float4*)&crow[tx * 4] = make_float4(cn[0], cn[1], cn[2], cn[3]);
        *(float4*)&hout[(h0 + th) * 64 + tx * 4] = make_float4(hn[0], hn[1], hn[2], hn[3]);
#pragma unroll
        for (int j = 0; j < 4; j++) {
            int b = tx * 4 + j;
            outp[((size_t)tt * BB + b) * (2 * HH) + dir * HH + h0 + th] = hn[j];
        }

        // Per-dir global barrier (monotonic counter, release/acquire)
        __threadfence();
        __syncthreads();
        if (tid == 0) {
            atomicAdd(bar, 1u);
            unsigned target = (unsigned)(t + 1) * 64u;
            unsigned v;
            do {
                asm volatile("ld.acquire.gpu.u32 %0, [%1];" : "=r"(v) : "l"(bar) : "memory");
            } while (v < target);
        }
        __syncthreads();
    }
}

// ---------------------------------------------------------------------------
// kernel_launch
// ---------------------------------------------------------------------------
extern "C" void kernel_launch(void* const* d_in, const int* in_sizes, int n_in,
                              void* d_out, int out_size)
{
    const float* x    = (const float*)d_in[0];
    const int*   mask = (const int*)  d_in[1];
    const float* w_ih = (const float*)d_in[2];
    const float* w_hh = (const float*)d_in[3];
    const float* b_ih = (const float*)d_in[4];
    const float* b_hh = (const float*)d_in[5];
    float* out = (float*)d_out;

    float* buf0 = nullptr;
    cudaGetSymbolAddress((void**)&buf0, g_buf0);

    cudaFuncSetAttribute(lstm_persistent,
                         cudaFuncAttributeMaxDynamicSharedMemorySize, SMEM_BYTES);

    dim3 gproj(MM / BM, FOURH / BN, 2);
    dim3 gpers(64, 2);

    for (int layer = 0; layer < 2; layer++) {
        const float* inp  = (layer == 0) ? x : buf0;
        float*       outl = (layer == 1) ? out : buf0;

        proj_kernel<<<gproj, 256>>>(
            inp,
            w_ih + (size_t)layer * 2 * FOURH * KP,
            b_ih + (size_t)layer * 2 * FOURH,
            b_hh + (size_t)layer * 2 * FOURH);

        zero_hc_kernel<<<(HH*BB + 255) / 256, 256>>>();

        lstm_persistent<<<gpers, 128, SMEM_BYTES>>>(
            w_hh + (size_t)layer * 2 * FOURH * HH,
            mask, outl);
    }
}

// round 5
// speedup vs baseline: 2.1006x; 1.4364x over previous
#include <cuda_runtime.h>
#include <cuda_bf16.h>
#include <math.h>
#include <stdint.h>

// Problem constants
#define TT     256
#define BB     64
#define HH     512
#define FOURH  2048
#define KP     1024
#define MM     (TT*BB)     // 16384

// ---------------------------------------------------------------------------
// Device scratch (static only — no cudaMalloc allowed)
// ---------------------------------------------------------------------------
__device__ float g_buf0[(size_t)MM*2*HH];            // layer-0 out / layer-1 in
__device__ float g_xproj[(size_t)2*MM*FOURH];        // input projections per dir
__device__ float g_h[2][2][HH*BB];                   // [dir][pingpong][h*64+b]  (TRANSPOSED)
__device__ float g_c[2][HH*BB];                      // [dir][h*64+b]
__device__ unsigned g_gbar[2];                       // per-dir step barrier counter

// bf16 split operands, plain row-major
__device__ __align__(16) __nv_bfloat16 g_Ahi[(size_t)MM*KP];
__device__ __align__(16) __nv_bfloat16 g_Alo[(size_t)MM*KP];
__device__ __align__(16) __nv_bfloat16 g_Whi[(size_t)4096*KP];
__device__ __align__(16) __nv_bfloat16 g_Wlo[(size_t)4096*KP];

// ---------------------------------------------------------------------------
// PTX helpers
// ---------------------------------------------------------------------------
__device__ __forceinline__ uint32_t smem_u32(const void* p) {
    uint32_t a;
    asm("{ .reg .u64 t; cvta.to.shared.u64 t, %1; cvt.u32.u64 %0, t; }" : "=r"(a) : "l"(p));
    return a;
}
__device__ __forceinline__ void mbar_init(uint32_t mb, uint32_t cnt) {
    asm volatile("mbarrier.init.shared.b64 [%0], %1;" :: "r"(mb), "r"(cnt) : "memory");
}
__device__ __forceinline__ void mbar_expect_tx(uint32_t mb, uint32_t bytes) {
    asm volatile("mbarrier.arrive.expect_tx.shared.b64 _, [%0], %1;" :: "r"(mb), "r"(bytes) : "memory");
}
__device__ __forceinline__ void bulk_g2s(uint32_t dst, const void* src, uint32_t bytes, uint32_t mb) {
    asm volatile("cp.async.bulk.shared::cta.global.mbarrier::complete_tx::bytes [%0], [%1], %2, [%3];"
                 :: "r"(dst), "l"(src), "r"(bytes), "r"(mb) : "memory");
}
__device__ __forceinline__ void mbar_wait(uint32_t mb, uint32_t parity) {
    uint32_t done;
    asm volatile("{\n\t.reg .pred p;\n\t"
        "mbarrier.try_wait.parity.acquire.cta.shared::cta.b64 p, [%1], %2;\n\t"
        "selp.b32 %0, 1, 0, p;\n\t}"
        : "=r"(done) : "r"(mb), "r"(parity) : "memory");
    while (!done) {
        asm volatile("{\n\t.reg .pred p;\n\t"
            "mbarrier.try_wait.parity.acquire.cta.shared::cta.b64 p, [%1], %2, 0x989680;\n\t"
            "selp.b32 %0, 1, 0, p;\n\t}"
            : "=r"(done) : "r"(mb), "r"(parity) : "memory");
    }
}
__device__ __forceinline__ void cpa16(uint32_t dst, const void* src) {
    asm volatile("cp.async.cg.shared.global [%0], [%1], 16;" :: "r"(dst), "l"(src) : "memory");
}
__device__ __forceinline__ void ldm_x4(uint32_t& r0, uint32_t& r1, uint32_t& r2, uint32_t& r3,
                                       uint32_t addr) {
    asm volatile("ldmatrix.sync.aligned.m8n8.x4.shared.b16 {%0,%1,%2,%3}, [%4];"
                 : "=r"(r0), "=r"(r1), "=r"(r2), "=r"(r3) : "r"(addr));
}
#define MMA_BF16(c, a, b0v, b1v) \
    asm volatile("mma.sync.aligned.m16n8k16.row.col.f32.bf16.bf16.f32 " \
        "{%0,%1,%2,%3}, {%4,%5,%6,%7}, {%8,%9}, {%0,%1,%2,%3};" \
        : "+f"((c)[0]), "+f"((c)[1]), "+f"((c)[2]), "+f"((c)[3]) \
        : "r"((a)[0]), "r"((a)[1]), "r"((a)[2]), "r"((a)[3]), "r"(b0v), "r"(b1v))

// ---------------------------------------------------------------------------
// Zero state + barrier counters before each layer
// ---------------------------------------------------------------------------
__global__ void zero_hc_kernel() {
    int i = blockIdx.x * blockDim.x + threadIdx.x;
    if (i < HH*BB) {
        g_h[0][0][i] = 0.f; g_h[0][1][i] = 0.f;
        g_h[1][0][i] = 0.f; g_h[1][1][i] = 0.f;
        g_c[0][i]    = 0.f; g_c[1][i]    = 0.f;
    }
    if (i < 2) g_gbar[i] = 0u;
}

// ---------------------------------------------------------------------------
// Pack fp32 -> hi/lo bf16 (row-major, 8 elems/thread)
// ---------------------------------------------------------------------------
__global__ __launch_bounds__(256) void pack_bf16(
    const float* __restrict__ src,
    __nv_bfloat16* __restrict__ hi, __nv_bfloat16* __restrict__ lo)
{
    size_t i = ((size_t)blockIdx.x * 256 + threadIdx.x) * 8;
    float4 v0 = *(const float4*)(src + i);
    float4 v1 = *(const float4*)(src + i + 4);
    float xv[8] = {v0.x, v0.y, v0.z, v0.w, v1.x, v1.y, v1.z, v1.w};
    uint32_t hp[4], lp[4];
#pragma unroll
    for (int e = 0; e < 4; e++) {
        __nv_bfloat16 h0 = __float2bfloat16(xv[2*e]);
        __nv_bfloat16 h1 = __float2bfloat16(xv[2*e+1]);
        __nv_bfloat16 l0 = __float2bfloat16(xv[2*e]   - __bfloat162float(h0));
        __nv_bfloat16 l1 = __float2bfloat16(xv[2*e+1] - __bfloat162float(h1));
        hp[e] = (uint32_t)__bfloat16_as_ushort(h0) | ((uint32_t)__bfloat16_as_ushort(h1) << 16);
        lp[e] = (uint32_t)__bfloat16_as_ushort(l0) | ((uint32_t)__bfloat16_as_ushort(l1) << 16);
    }
    *(uint4*)(hi + i) = make_uint4(hp[0], hp[1], hp[2], hp[3]);
    *(uint4*)(lo + i) = make_uint4(lp[0], lp[1], lp[2], lp[3]);
}

// ---------------------------------------------------------------------------
// HMMA projection GEMM: C = A · W^T + bias, split bf16, fp32 accum.
// CTA tile 128m x 128n x 64k, 256 threads (8 warps, 2m x 4n of 64x32).
// smem: 2 stages x {Ahi,Alo,Whi,Wlo} 128 rows x 128B data, 144B padded stride.
// grid = (128 m-blocks, 32 n-blocks); n covers dir0 2048 cols then dir1.
// ---------------------------------------------------------------------------
#define ROWB   144
#define TILEB  (128*ROWB)                 // 18432
#define STGB   (4*TILEB)                  // 73728
#define OFF_BIAS (2*STGB)                 // 147456
#define SMEM_PROJ (OFF_BIAS + 512)        // 147968

__global__ __launch_bounds__(256, 1) void proj_mma(
    const __nv_bfloat16* __restrict__ Ah, const __nv_bfloat16* __restrict__ Al,
    const __nv_bfloat16* __restrict__ Wh, const __nv_bfloat16* __restrict__ Wl,
    const float* __restrict__ b1, const float* __restrict__ b2)
{
    extern __shared__ __align__(128) char smp[];
    const uint32_t sb = smem_u32(smp);
    float* bias = (float*)(smp + OFF_BIAS);

    const int tid  = threadIdx.x;
    const int lane = tid & 31;
    const int w    = tid >> 5;
    const int m0   = blockIdx.x * 128;
    const int nG   = blockIdx.y * 128;
    const int dir  = nG >> 11;
    const int nd   = nG & 2047;
    const int wm   = (w >> 2) * 64;
    const int wn   = (w & 3) * 32;

    if (tid < 128) bias[tid] = b1[dir * FOURH + nd + tid] + b2[dir * FOURH + nd + tid];

    // cp.async mapping: 16 chunks/thread/stage; chunk = tile(2b)|row(7b)|col8(3b)
    int cr[16], cc[16], ct[16];
#pragma unroll
    for (int i = 0; i < 16; i++) {
        int c = i * 256 + tid;
        ct[i] = c >> 10; cr[i] = (c >> 3) & 127; cc[i] = c & 7;
    }

    auto load_stage = [&](int s, int kt) {
        uint32_t base = sb + (uint32_t)s * STGB;
#pragma unroll
        for (int i = 0; i < 16; i++) {
            uint32_t dst = base + (uint32_t)ct[i] * TILEB + (uint32_t)cr[i] * ROWB + (uint32_t)cc[i] * 16;
            const __nv_bfloat16* g;
            if (ct[i] == 0)      g = Ah + (size_t)(m0 + cr[i]) * KP + kt * 64 + cc[i] * 8;
            else if (ct[i] == 1) g = Al + (size_t)(m0 + cr[i]) * KP + kt * 64 + cc[i] * 8;
            else if (ct[i] == 2) g = Wh + (size_t)(nG + cr[i]) * KP + kt * 64 + cc[i] * 8;
            else                 g = Wl + (size_t)(nG + cr[i]) * KP + kt * 64 + cc[i] * 8;
            cpa16(dst, g);
        }
        asm volatile("cp.async.commit_group;" ::: "memory");
    };

    float c[4][4][4];
#pragma unroll
    for (int mi = 0; mi < 4; mi++)
#pragma unroll
        for (int ni = 0; ni < 4; ni++)
#pragma unroll
            for (int j = 0; j < 4; j++) c[mi][ni][j] = 0.f;

    // ldmatrix per-thread row/byte components
    const uint32_t aRow  = (uint32_t)(wm + (lane & 15));
    const uint32_t aByte = (lane & 16) ? 16u : 0u;
    const uint32_t bRow  = (uint32_t)(wn + (lane & 7) + ((lane & 16) ? 8 : 0));
    const uint32_t bByte = (lane & 8) ? 16u : 0u;

    load_stage(0, 0);

    for (int kt = 0; kt < 16; kt++) {
        if (kt < 15) {
            load_stage((kt + 1) & 1, kt + 1);
            asm volatile("cp.async.wait_group 1;" ::: "memory");
        } else {
            asm volatile("cp.async.wait_group 0;" ::: "memory");
        }
        __syncthreads();

        uint32_t st = sb + (uint32_t)(kt & 1) * STGB;
#pragma unroll
        for (int ks = 0; ks < 4; ks++) {
            uint32_t kb = (uint32_t)(ks * 32);
            uint32_t ah[4][4], al[4][4], bh[2][4], bl[2][4];
#pragma unroll
            for (int mi = 0; mi < 4; mi++) {
                uint32_t ra = (aRow + mi * 16) * ROWB + kb + aByte;
                ldm_x4(ah[mi][0], ah[mi][1], ah[mi][2], ah[mi][3], st + ra);
                ldm_x4(al[mi][0], al[mi][1], al[mi][2], al[mi][3], st + TILEB + ra);
            }
#pragma unroll
            for (int np = 0; np < 2; np++) {
                uint32_t rb = (bRow + np * 16) * ROWB + kb + bByte;
                ldm_x4(bh[np][0], bh[np][1], bh[np][2], bh[np][3], st + 2 * TILEB + rb);
                ldm_x4(bl[np][0], bl[np][1], bl[np][2], bl[np][3], st + 3 * TILEB + rb);
            }
#pragma unroll
            for (int mi = 0; mi < 4; mi++)
#pragma unroll
                for (int ni = 0; ni < 4; ni++) {
                    int np = ni >> 1, o = (ni & 1) * 2;
                    MMA_BF16(c[mi][ni], ah[mi], bh[np][o], bh[np][o + 1]);
                    MMA_BF16(c[mi][ni], ah[mi], bl[np][o], bl[np][o + 1]);
                    MMA_BF16(c[mi][ni], al[mi], bh[np][o], bh[np][o + 1]);
                }
        }
        __syncthreads();
    }

    // Epilogue: bias + store fp32
    float* outD = g_xproj + (size_t)dir * MM * FOURH;
#pragma unroll
    for (int mi = 0; mi < 4; mi++) {
        int row0 = m0 + wm + mi * 16 + (lane >> 2);
#pragma unroll
        for (int ni = 0; ni < 4; ni++) {
            int colL = wn + ni * 8 + (lane & 3) * 2;
            float bx = bias[colL], by = bias[colL + 1];
            float2 v0 = make_float2(c[mi][ni][0] + bx, c[mi][ni][1] + by);
            float2 v1 = make_float2(c[mi][ni][2] + bx, c[mi][ni][3] + by);
            *(float2*)&outD[(size_t)row0 * FOURH + nd + colL] = v0;
            *(float2*)&outD[(size_t)(row0 + 8) * FOURH + nd + colL] = v1;
        }
    }
}

// ---------------------------------------------------------------------------
// Persistent recurrence: 256 threads, warp = one h (8 h/block), lane = 2 batches.
// grid = (64 h-blocks, 2 dirs). W slice in smem once; h streamed per step.
// ---------------------------------------------------------------------------
#define SM_WS 0                         // 16384 floats (8h x 4g x 512k)
#define SM_HS 16384                     // 32768 floats (512k x 64b)
#define SM_XS 49152                     // 2048 floats (4g x 8h x 64b)
#define SM_MS 51200                     // 64 ints
#define SM_MBAR_BYTE ((SM_MS + 64) * 4) // 205056
#define SMEM_LSTM (SM_MBAR_BYTE + 64)   // 205120

__device__ __forceinline__ float sig_(float x) {
    return __fdividef(1.f, 1.f + __expf(-x));
}

__global__ __launch_bounds__(256, 1) void lstm_persistent(
    const float* __restrict__ Whhl,   // [2][4H][H]
    const int*   __restrict__ mask,   // [B][T]
    float*       __restrict__ outp)   // [T][B][2H]
{
    extern __shared__ float sm[];
    float* ws = sm + SM_WS;
    float* hs = sm + SM_HS;
    float* xs = sm + SM_XS;
    int*   ms = (int*)(sm + SM_MS);
    const uint32_t smbase = smem_u32(sm);
    const uint32_t mbar0  = smbase + SM_MBAR_BYTE;

    const int dir = blockIdx.y;
    const int h0  = blockIdx.x * 8;
    const int tid = threadIdx.x;
    const int lane = tid & 31;
    const int wid  = tid >> 5;          // 0..7 = h within block
    const int lane2 = lane * 2;

    const float* W   = Whhl + (size_t)dir * FOURH * HH;
    const float* xpD = g_xproj + (size_t)dir * MM * FOURH;

    // W slice once: ws[(hh*4+g)*512 + k] <- W[g*512 + h0 + hh][k]
    for (int i = tid; i < 4096; i += 256) {
        int r = i >> 7, q = i & 127;
        int hh = r >> 2, g = r & 3;
        float4 v = *(const float4*)&W[(size_t)(g * HH + h0 + hh) * HH + q * 4];
        *(float4*)&ws[r * 512 + q * 4] = v;
    }
    if (tid == 0) {
        for (int ch = 0; ch < 4; ch++) mbar_init(mbar0 + ch * 8, 1);
    }
    __syncthreads();

    unsigned* bar = &g_gbar[dir];
    const float* wsrow = ws + wid * 2048;

    for (int t = 0; t < TT; t++) {
        const int tt = dir ? (TT - 1 - t) : t;
        const float* hin  = g_h[dir][t & 1];
        float*       hout = g_h[dir][(t + 1) & 1];

        if (tid == 0) {
            asm volatile("fence.proxy.async.shared::cta;" ::: "memory");
#pragma unroll
            for (int ch = 0; ch < 4; ch++) {
                uint32_t mb = mbar0 + ch * 8;
                mbar_expect_tx(mb, 32768u);
                bulk_g2s(smbase + (SM_HS + ch * 8192) * 4, hin + ch * 8192, 32768u, mb);
            }
        }

        // Stage xproj slice [4g][8h][64b] and mask
        const float* xp = xpD + (size_t)tt * BB * FOURH;
        for (int i = tid; i < 512; i += 256) {
            int b = i >> 3, r = i & 7;
            int g = r >> 1, hq = r & 1;
            float4 v = *(const float4*)&xp[(size_t)b * FOURH + g * HH + h0 + hq * 4];
            xs[(g * 8 + hq * 4 + 0) * 64 + b] = v.x;
            xs[(g * 8 + hq * 4 + 1) * 64 + b] = v.y;
            xs[(g * 8 + hq * 4 + 2) * 64 + b] = v.z;
            xs[(g * 8 + hq * 4 + 3) * 64 + b] = v.w;
        }
        if (tid < 64) ms[tid] = mask[tid * TT + tt];

        // GEMM: thread = (h = h0+wid, b pair = lane2, lane2+1), 4 gates
        float a0x = 0.f, a0y = 0.f, a1x = 0.f, a1y = 0.f;
        float a2x = 0.f, a2y = 0.f, a3x = 0.f, a3y = 0.f;
        const uint32_t par = (uint32_t)(t & 1);
#pragma unroll
        for (int ch = 0; ch < 4; ch++) {
            mbar_wait(mbar0 + ch * 8, par);
            const float* hc = hs + ch * 8192 + lane2;
            const float* wc = wsrow + ch * 128;
#pragma unroll 4
            for (int kk = 0; kk < 128; kk += 4) {
                float4 w0 = *(const float4*)&wc[kk];
                float4 w1 = *(const float4*)&wc[512 + kk];
                float4 w2 = *(const float4*)&wc[1024 + kk];
                float4 w3 = *(const float4*)&wc[1536 + kk];
                const float* hb = hc + kk * 64;
                float2 hv0 = *(const float2*)(hb);
                float2 hv1 = *(const float2*)(hb + 64);
                float2 hv2 = *(const float2*)(hb + 128);
                float2 hv3 = *(const float2*)(hb + 192);
                a0x += w0.x * hv0.x; a0y += w0.x * hv0.y;
                a1x += w1.x * hv0.x; a1y += w1.x * hv0.y;
                a2x += w2.x * hv0.x; a2y += w2.x * hv0.y;
                a3x += w3.x * hv0.x; a3y += w3.x * hv0.y;
                a0x += w0.y * hv1.x; a0y += w0.y * hv1.y;
                a1x += w1.y * hv1.x; a1y += w1.y * hv1.y;
                a2x += w2.y * hv1.x; a2y += w2.y * hv1.y;
                a3x += w3.y * hv1.x; a3y += w3.y * hv1.y;
                a0x += w0.z * hv2.x; a0y += w0.z * hv2.y;
                a1x += w1.z * hv2.x; a1y += w1.z * hv2.y;
                a2x += w2.z * hv2.x; a2y += w2.z * hv2.y;
                a3x += w3.z * hv2.x; a3y += w3.z * hv2.y;
                a0x += w0.w * hv3.x; a0y += w0.w * hv3.y;
                a1x += w1.w * hv3.x; a1y += w1.w * hv3.y;
                a2x += w2.w * hv3.x; a2y += w2.w * hv3.y;
                a3x += w3.w * hv3.x; a3y += w3.w * hv3.y;
            }
        }

        __syncthreads();   // xs staging complete before epilogue reads

        // LSTM cell epilogue: 2 batches per thread
        float2 xg0 = *(const float2*)&xs[(0 * 8 + wid) * 64 + lane2];
        float2 xg1 = *(const float2*)&xs[(1 * 8 + wid) * 64 + lane2];
        float2 xg2 = *(const float2*)&xs[(2 * 8 + wid) * 64 + lane2];
        float2 xg3 = *(const float2*)&xs[(3 * 8 + wid) * 64 + lane2];
        float* crow = &g_c[dir][(h0 + wid) * 64];
        float2 cv = *(const float2*)&crow[lane2];

        float gi[2] = {a0x + xg0.x, a0y + xg0.y};
        float gf[2] = {a1x + xg1.x, a1y + xg1.y};
        float gg[2] = {a2x + xg2.x, a2y + xg2.y};
        float go[2] = {a3x + xg3.x, a3y + xg3.y};
        float co[2] = {cv.x, cv.y};

        float hn[2], cn[2];
#pragma unroll
        for (int j = 0; j < 2; j++) {
            float si = sig_(gi[j]);
            float sf = sig_(gf[j]);
            float so = sig_(go[j]);
            float tg = 2.f * sig_(2.f * gg[j]) - 1.f;   // tanh
            float c2 = sf * co[j] + si * tg;
            float tc = 2.f * sig_(2.f * c2) - 1.f;      // tanh
            float h2 = so * tc;
            float m  = (float)ms[lane2 + j];
            cn[j] = c2 * m;
            hn[j] = h2 * m;
        }

        *(float2*)&crow[lane2] = make_float2(cn[0], cn[1]);
        *(float2*)&hout[(h0 + wid) * 64 + lane2] = make_float2(hn[0], hn[1]);
#pragma unroll
        for (int j = 0; j < 2; j++) {
            int b = lane2 + j;
            outp[((size_t)tt * BB + b) * (2 * HH) + dir * HH + h0 + wid] = hn[j];
        }

        // Per-dir global barrier (monotonic counter, release/acquire)
        __threadfence();
        __syncthreads();
        if (tid == 0) {
            atomicAdd(bar, 1u);
            unsigned target = (unsigned)(t + 1) * 64u;
            unsigned v;
            do {
                asm volatile("ld.acquire.gpu.u32 %0, [%1];" : "=r"(v) : "l"(bar) : "memory");
            } while (v < target);
        }
        __syncthreads();
    }
}

// ---------------------------------------------------------------------------
// kernel_launch
// ---------------------------------------------------------------------------
extern "C" void kernel_launch(void* const* d_in, const int* in_sizes, int n_in,
                              void* d_out, int out_size)
{
    const float* x    = (const float*)d_in[0];
    const int*   mask = (const int*)  d_in[1];
    const float* w_ih = (const float*)d_in[2];
    const float* w_hh = (const float*)d_in[3];
    const float* b_ih = (const float*)d_in[4];
    const float* b_hh = (const float*)d_in[5];
    float* out = (float*)d_out;

    float* buf0 = nullptr;
    cudaGetSymbolAddress((void**)&buf0, g_buf0);
    __nv_bfloat16 *pAh, *pAl, *pWh, *pWl;
    cudaGetSymbolAddress((void**)&pAh, g_Ahi);
    cudaGetSymbolAddress((void**)&pAl, g_Alo);
    cudaGetSymbolAddress((void**)&pWh, g_Whi);
    cudaGetSymbolAddress((void**)&pWl, g_Wlo);

    cudaFuncSetAttribute(lstm_persistent,
                         cudaFuncAttributeMaxDynamicSharedMemorySize, SMEM_LSTM);
    cudaFuncSetAttribute(proj_mma,
                         cudaFuncAttributeMaxDynamicSharedMemorySize, SMEM_PROJ);

    dim3 gproj(128, 32);
    dim3 gpers(64, 2);

    for (int layer = 0; layer < 2; layer++) {
        const float* inp  = (layer == 0) ? x : buf0;
        float*       outl = (layer == 1) ? out : buf0;

        pack_bf16<<<8192, 256>>>(inp, pAh, pAl);
        pack_bf16<<<2048, 256>>>(w_ih + (size_t)layer * 2 * FOURH * KP, pWh, pWl);

        proj_mma<<<gproj, 256, SMEM_PROJ>>>(
            pAh, pAl, pWh, pWl,
            b_ih + (size_t)layer * 2 * FOURH,
            b_hh + (size_t)layer * 2 * FOURH);

        zero_hc_kernel<<<(HH*BB + 255) / 256, 256>>>();

        lstm_persistent<<<gpers, 256, SMEM_LSTM>>>(
            w_hh + (size_t)layer * 2 * FOURH * HH,
            mask, outl);
    }
}

// round 6
// speedup vs baseline: 3.0190x; 1.4372x over previous
#include <cuda_runtime.h>
#include <cuda_bf16.h>
#include <math.h>
#include <stdint.h>

// Problem constants
#define TT     256
#define BB     64
#define HH     512
#define FOURH  2048
#define KP     1024
#define MM     (TT*BB)     // 16384

// ---------------------------------------------------------------------------
// Device scratch (static only)
// ---------------------------------------------------------------------------
__device__ float g_buf0[(size_t)MM*2*HH];            // layer-0 out / layer-1 in
__device__ float g_xproj[(size_t)2*MM*FOURH];        // input projections, pr-packed cols
__device__ unsigned g_gbar[2];                       // per-dir step barrier counter

// proj operands: bf16 split, row-major
__device__ __align__(16) __nv_bfloat16 g_Ahi[(size_t)MM*KP];
__device__ __align__(16) __nv_bfloat16 g_Alo[(size_t)MM*KP];
__device__ __align__(16) __nv_bfloat16 g_Whi[(size_t)4096*KP];
__device__ __align__(16) __nv_bfloat16 g_Wlo[(size_t)4096*KP];

// recurrence W_hh: per (dir, block) slab: hi[32][1040B] + lo[32][1040B] = 66560B
#define WSLAB 66560
#define WLO   33280
__device__ __align__(128) char g_Wr[(size_t)2*64*WSLAB];

// recurrence h state: [dir][ping][chunk4]{ hi[64][272B], lo[64][272B] }
#define CH_HALF 17408
#define CH_SZ   34816
#define HA_SZ   (4*CH_SZ)    // 139264 per (dir,ping)
__device__ __align__(128) char g_hA[(size_t)2*2*HA_SZ];

// ---------------------------------------------------------------------------
// PTX helpers
// ---------------------------------------------------------------------------
__device__ __forceinline__ uint32_t smem_u32(const void* p) {
    uint32_t a;
    asm("{ .reg .u64 t; cvta.to.shared.u64 t, %1; cvt.u32.u64 %0, t; }" : "=r"(a) : "l"(p));
    return a;
}
__device__ __forceinline__ void mbar_init(uint32_t mb, uint32_t cnt) {
    asm volatile("mbarrier.init.shared.b64 [%0], %1;" :: "r"(mb), "r"(cnt) : "memory");
}
__device__ __forceinline__ void mbar_expect_tx(uint32_t mb, uint32_t bytes) {
    asm volatile("mbarrier.arrive.expect_tx.shared.b64 _, [%0], %1;" :: "r"(mb), "r"(bytes) : "memory");
}
__device__ __forceinline__ void bulk_g2s(uint32_t dst, const void* src, uint32_t bytes, uint32_t mb) {
    asm volatile("cp.async.bulk.shared::cta.global.mbarrier::complete_tx::bytes [%0], [%1], %2, [%3];"
                 :: "r"(dst), "l"(src), "r"(bytes), "r"(mb) : "memory");
}
__device__ __forceinline__ void mbar_wait(uint32_t mb, uint32_t parity) {
    uint32_t done;
    asm volatile("{\n\t.reg .pred p;\n\t"
        "mbarrier.try_wait.parity.acquire.cta.shared::cta.b64 p, [%1], %2;\n\t"
        "selp.b32 %0, 1, 0, p;\n\t}"
        : "=r"(done) : "r"(mb), "r"(parity) : "memory");
    while (!done) {
        asm volatile("{\n\t.reg .pred p;\n\t"
            "mbarrier.try_wait.parity.acquire.cta.shared::cta.b64 p, [%1], %2, 0x989680;\n\t"
            "selp.b32 %0, 1, 0, p;\n\t}"
            : "=r"(done) : "r"(mb), "r"(parity) : "memory");
    }
}
__device__ __forceinline__ void cpa16(uint32_t dst, const void* src) {
    asm volatile("cp.async.cg.shared.global [%0], [%1], 16;" :: "r"(dst), "l"(src) : "memory");
}
__device__ __forceinline__ void ldm_x4(uint32_t& r0, uint32_t& r1, uint32_t& r2, uint32_t& r3,
                                       uint32_t addr) {
    asm volatile("ldmatrix.sync.aligned.m8n8.x4.shared.b16 {%0,%1,%2,%3}, [%4];"
                 : "=r"(r0), "=r"(r1), "=r"(r2), "=r"(r3) : "r"(addr));
}
#define MMA_BF16(c, a, b0v, b1v) \
    asm volatile("mma.sync.aligned.m16n8k16.row.col.f32.bf16.bf16.f32 " \
        "{%0,%1,%2,%3}, {%4,%5,%6,%7}, {%8,%9}, {%0,%1,%2,%3};" \
        : "+f"((c)[0]), "+f"((c)[1]), "+f"((c)[2]), "+f"((c)[3]) \
        : "r"((a)[0]), "r"((a)[1]), "r"((a)[2]), "r"((a)[3]), "r"(b0v), "r"(b1v))

__device__ __forceinline__ float sig_(float x) {
    return __fdividef(1.f, 1.f + __expf(-x));
}
__device__ __forceinline__ uint32_t pack_hilo(float a, float b, uint32_t& lo) {
    __nv_bfloat16 h0 = __float2bfloat16(a);
    __nv_bfloat16 h1 = __float2bfloat16(b);
    __nv_bfloat16 l0 = __float2bfloat16(a - __bfloat162float(h0));
    __nv_bfloat16 l1 = __float2bfloat16(b - __bfloat162float(h1));
    lo = (uint32_t)__bfloat16_as_ushort(l0) | ((uint32_t)__bfloat16_as_ushort(l1) << 16);
    return (uint32_t)__bfloat16_as_ushort(h0) | ((uint32_t)__bfloat16_as_ushort(h1) << 16);
}

// ---------------------------------------------------------------------------
// Zero h slot 0 (both dirs) + barrier counters
// ---------------------------------------------------------------------------
__global__ void zero_state() {
    uint32_t i = blockIdx.x * 256 + threadIdx.x;     // 0..34815 floats
    float* p = (float*)g_hA;
    if (i < HA_SZ / 4) {
        p[i] = 0.f;                                  // dir0 ping0
        p[i + (2 * HA_SZ) / 4] = 0.f;                // dir1 ping0
    }
    if (i < 2) g_gbar[i] = 0u;
}

// ---------------------------------------------------------------------------
// Pack fp32 -> hi/lo bf16 (row-major, 8 elems/thread) — proj operands
// ---------------------------------------------------------------------------
__global__ __launch_bounds__(256) void pack_bf16(
    const float* __restrict__ src,
    __nv_bfloat16* __restrict__ hi, __nv_bfloat16* __restrict__ lo)
{
    size_t i = ((size_t)blockIdx.x * 256 + threadIdx.x) * 8;
    float4 v0 = *(const float4*)(src + i);
    float4 v1 = *(const float4*)(src + i + 4);
    float xv[8] = {v0.x, v0.y, v0.z, v0.w, v1.x, v1.y, v1.z, v1.w};
    uint32_t hp[4], lp[4];
#pragma unroll
    for (int e = 0; e < 4; e++) hp[e] = pack_hilo(xv[2*e], xv[2*e+1], lp[e]);
    *(uint4*)(hi + i) = make_uint4(hp[0], hp[1], hp[2], hp[3]);
    *(uint4*)(lo + i) = make_uint4(lp[0], lp[1], lp[2], lp[3]);
}

// ---------------------------------------------------------------------------
// Pack W_hh into per-block slabs: row pr=hh*4+g  <-  W[g*512 + blk*8+hh][k]
// grid = 128 (dir = b>>6, blk = b&63), 256 threads
// ---------------------------------------------------------------------------
__global__ __launch_bounds__(256) void pack_Wr(const float* __restrict__ whh) {
    const int dir = blockIdx.x >> 6, blk = blockIdx.x & 63;
    char* slab = g_Wr + (size_t)(dir * 64 + blk) * WSLAB;
    for (int i = threadIdx.x; i < 8192; i += 256) {
        int r = i >> 8;                 // packed row 0..31
        int k2 = (i & 255) * 2;         // k pair
        int hh = r >> 2, g = r & 3;
        int grow = g * HH + blk * 8 + hh;
        float2 v = *(const float2*)&whh[((size_t)dir * FOURH + grow) * HH + k2];
        uint32_t lo, hi = pack_hilo(v.x, v.y, lo);
        *(uint32_t*)(slab + r * 1040 + k2 * 2) = hi;
        *(uint32_t*)(slab + WLO + r * 1040 + k2 * 2) = lo;
    }
}

// ---------------------------------------------------------------------------
// HMMA projection GEMM (epilogue writes pr-packed cols). Otherwise R5-proven.
// ---------------------------------------------------------------------------
#define ROWB   144
#define TILEB  (128*ROWB)
#define STGB   (4*TILEB)
#define OFF_BIAS (2*STGB)
#define SMEM_PROJ (OFF_BIAS + 512)

__global__ __launch_bounds__(256, 1) void proj_mma(
    const __nv_bfloat16* __restrict__ Ah, const __nv_bfloat16* __restrict__ Al,
    const __nv_bfloat16* __restrict__ Wh, const __nv_bfloat16* __restrict__ Wl,
    const float* __restrict__ b1, const float* __restrict__ b2)
{
    extern __shared__ __align__(128) char smp[];
    const uint32_t sb = smem_u32(smp);
    float* bias = (float*)(smp + OFF_BIAS);

    const int tid  = threadIdx.x;
    const int lane = tid & 31;
    const int w    = tid >> 5;
    const int m0   = blockIdx.x * 128;
    const int nG   = blockIdx.y * 128;
    const int dir  = nG >> 11;
    const int nd   = nG & 2047;
    const int wm   = (w >> 2) * 64;
    const int wn   = (w & 3) * 32;

    if (tid < 128) bias[tid] = b1[dir * FOURH + nd + tid] + b2[dir * FOURH + nd + tid];

    int cr[16], cc[16], ct[16];
#pragma unroll
    for (int i = 0; i < 16; i++) {
        int c = i * 256 + tid;
        ct[i] = c >> 10; cr[i] = (c >> 3) & 127; cc[i] = c & 7;
    }

    auto load_stage = [&](int s, int kt) {
        uint32_t base = sb + (uint32_t)s * STGB;
#pragma unroll
        for (int i = 0; i < 16; i++) {
            uint32_t dst = base + (uint32_t)ct[i] * TILEB + (uint32_t)cr[i] * ROWB + (uint32_t)cc[i] * 16;
            const __nv_bfloat16* g;
            if (ct[i] == 0)      g = Ah + (size_t)(m0 + cr[i]) * KP + kt * 64 + cc[i] * 8;
            else if (ct[i] == 1) g = Al + (size_t)(m0 + cr[i]) * KP + kt * 64 + cc[i] * 8;
            else if (ct[i] == 2) g = Wh + (size_t)(nG + cr[i]) * KP + kt * 64 + cc[i] * 8;
            else                 g = Wl + (size_t)(nG + cr[i]) * KP + kt * 64 + cc[i] * 8;
            cpa16(dst, g);
        }
        asm volatile("cp.async.commit_group;" ::: "memory");
    };

    float c[4][4][4];
#pragma unroll
    for (int mi = 0; mi < 4; mi++)
#pragma unroll
        for (int ni = 0; ni < 4; ni++)
#pragma unroll
            for (int j = 0; j < 4; j++) c[mi][ni][j] = 0.f;

    const uint32_t aRow  = (uint32_t)(wm + (lane & 15));
    const uint32_t aByte = (lane & 16) ? 16u : 0u;
    const uint32_t bRow  = (uint32_t)(wn + (lane & 7) + ((lane & 16) ? 8 : 0));
    const uint32_t bByte = (lane & 8) ? 16u : 0u;

    load_stage(0, 0);

    for (int kt = 0; kt < 16; kt++) {
        if (kt < 15) {
            load_stage((kt + 1) & 1, kt + 1);
            asm volatile("cp.async.wait_group 1;" ::: "memory");
        } else {
            asm volatile("cp.async.wait_group 0;" ::: "memory");
        }
        __syncthreads();

        uint32_t st = sb + (uint32_t)(kt & 1) * STGB;
#pragma unroll
        for (int ks = 0; ks < 4; ks++) {
            uint32_t kb = (uint32_t)(ks * 32);
            uint32_t ah[4][4], al[4][4], bh[2][4], bl[2][4];
#pragma unroll
            for (int mi = 0; mi < 4; mi++) {
                uint32_t ra = (aRow + mi * 16) * ROWB + kb + aByte;
                ldm_x4(ah[mi][0], ah[mi][1], ah[mi][2], ah[mi][3], st + ra);
                ldm_x4(al[mi][0], al[mi][1], al[mi][2], al[mi][3], st + TILEB + ra);
            }
#pragma unroll
            for (int np = 0; np < 2; np++) {
                uint32_t rb = (bRow + np * 16) * ROWB + kb + bByte;
                ldm_x4(bh[np][0], bh[np][1], bh[np][2], bh[np][3], st + 2 * TILEB + rb);
                ldm_x4(bl[np][0], bl[np][1], bl[np][2], bl[np][3], st + 3 * TILEB + rb);
            }
#pragma unroll
            for (int mi = 0; mi < 4; mi++)
#pragma unroll
                for (int ni = 0; ni < 4; ni++) {
                    int np = ni >> 1, o = (ni & 1) * 2;
                    MMA_BF16(c[mi][ni], ah[mi], bh[np][o], bh[np][o + 1]);
                    MMA_BF16(c[mi][ni], ah[mi], bl[np][o], bl[np][o + 1]);
                    MMA_BF16(c[mi][ni], al[mi], bh[np][o], bh[np][o + 1]);
                }
        }
        __syncthreads();
    }

    // Epilogue: bias + scatter to pr-packed layout: pr = (n&511)*4 + (n>>9)
    float* outD = g_xproj + (size_t)dir * MM * FOURH;
#pragma unroll
    for (int mi = 0; mi < 4; mi++) {
        int row0 = m0 + wm + mi * 16 + (lane >> 2);
#pragma unroll
        for (int ni = 0; ni < 4; ni++) {
            int colL = wn + ni * 8 + (lane & 3) * 2;
            float bx = bias[colL], by = bias[colL + 1];
            int n0 = nd + colL;
            int pr0 = (n0 & 511) * 4 + (n0 >> 9);
            int pr1 = ((n0 + 1) & 511) * 4 + ((n0 + 1) >> 9);
            outD[(size_t)row0 * FOURH + pr0] = c[mi][ni][0] + bx;
            outD[(size_t)row0 * FOURH + pr1] = c[mi][ni][1] + by;
            outD[(size_t)(row0 + 8) * FOURH + pr0] = c[mi][ni][2] + bx;
            outD[(size_t)(row0 + 8) * FOURH + pr1] = c[mi][ni][3] + by;
        }
    }
}

// ---------------------------------------------------------------------------
// Persistent HMMA recurrence. grid = (64 blk, 2 dir), 256 threads (8 warps).
// Block owns 8 h x 4 gates (N=32 pr-cols). W slice resident in smem.
// h round-trips via bf16 hi/lo 4-chunk global, bulk-copied per step.
// Warp tile: 4m x 2n of m16n16. c-state in registers.
// ---------------------------------------------------------------------------
#define SM_A  0                         // 4 chunks x (hi 17408 + lo 17408)
#define SM_W  139264                    // hi[32][1040] + lo[32][1040]
#define SM_C  205824                    // sC[64][36] fp32
#define SM_X  215040                    // xs[64][36] fp32
#define SM_MB 224256                    // 5 mbarriers
#define SMEM_LSTM 224320

__global__ __launch_bounds__(256, 1) void lstm_mma(
    const int* __restrict__ mask,     // [B][T]
    float*     __restrict__ outp)     // [T][B][2H]
{
    extern __shared__ __align__(128) char sm[];
    const uint32_t sb = smem_u32(sm);
    float* sC = (float*)(sm + SM_C);
    float* xs = (float*)(sm + SM_X);

    const int dir = blockIdx.y;
    const int blk = blockIdx.x;
    const int tid = threadIdx.x;
    const int lane = tid & 31;
    const int w = tid >> 5;
    const int wm = (w >> 1) * 16;       // m-offset (batch)
    const int wn = (w & 1) * 16;        // n-offset (pr)

    const uint32_t mb0 = sb + SM_MB;    // chunk mbars +0..+24, W mbar +32
    if (tid == 0) {
        for (int c = 0; c < 5; c++) mbar_init(mb0 + c * 8, 1);
        asm volatile("fence.proxy.async.shared::cta;" ::: "memory");
        mbar_expect_tx(mb0 + 32, (uint32_t)WSLAB);
        bulk_g2s(sb + SM_W, g_Wr + (size_t)(dir * 64 + blk) * WSLAB, (uint32_t)WSLAB, mb0 + 32);
    }
    __syncthreads();
    mbar_wait(mb0 + 32, 0);

    // ldmatrix per-thread addressing (verbatim from proven proj kernel)
    const uint32_t aRow  = (uint32_t)(wm + (lane & 15));
    const uint32_t aByte = (lane & 16) ? 16u : 0u;
    const uint32_t bRow  = (uint32_t)(wn + (lane & 7) + ((lane & 16) ? 8 : 0));
    const uint32_t bByte = (lane & 8) ? 16u : 0u;

    const float* xprjD = g_xproj + (size_t)dir * MM * FOURH;
    unsigned* bar = &g_gbar[dir];
    const char* hbase = g_hA + (size_t)dir * 2 * HA_SZ;

    // cell mapping: cells idx = tid, tid+256 -> b = idx&63, hh = idx>>6
    const int cb  = tid & 63;
    const int ch0 = tid >> 6;           // 0..3
    const int kloc0 = (blk & 15) * 8 + ch0;
    const int chunk = blk >> 4;
    float cst[2] = {0.f, 0.f};

    for (int t = 0; t < TT; t++) {
        const int tt = dir ? (TT - 1 - t) : t;

        if (tid == 0) {
            asm volatile("fence.proxy.async.shared::cta;" ::: "memory");
            const char* src = hbase + (size_t)(t & 1) * HA_SZ;
#pragma unroll
            for (int c = 0; c < 4; c++) {
                mbar_expect_tx(mb0 + c * 8, (uint32_t)CH_SZ);
                bulk_g2s(sb + SM_A + c * CH_SZ, src + c * CH_SZ, (uint32_t)CH_SZ, mb0 + c * 8);
            }
        }

        // Prefetch xproj slice + mask (LDG latency hidden behind MMA)
        float4 xr[2];
        {
            int f0 = tid, f1 = tid + 256;
            xr[0] = *(const float4*)&xprjD[((size_t)tt * BB + (f0 >> 3)) * FOURH + blk * 32 + (f0 & 7) * 4];
            xr[1] = *(const float4*)&xprjD[((size_t)tt * BB + (f1 >> 3)) * FOURH + blk * 32 + (f1 & 7) * 4];
        }
        const float mreg = (float)mask[cb * TT + tt];

        // MMA: C[64b x 32pr] = h[64x512] . Wslice^T   (split bf16, 3 products)
        float cf[2][4];
#pragma unroll
        for (int ni = 0; ni < 2; ni++)
#pragma unroll
            for (int j = 0; j < 4; j++) cf[ni][j] = 0.f;

        const uint32_t par = (uint32_t)(t & 1);
#pragma unroll
        for (int c = 0; c < 4; c++) {
            mbar_wait(mb0 + c * 8, par);
            uint32_t baseA = sb + SM_A + (uint32_t)c * CH_SZ;
#pragma unroll
            for (int ks = 0; ks < 8; ks++) {
                uint32_t ah[4], al[4], bh[4], bl[4];
                uint32_t ra = aRow * 272 + (uint32_t)ks * 32 + aByte;
                ldm_x4(ah[0], ah[1], ah[2], ah[3], baseA + ra);
                ldm_x4(al[0], al[1], al[2], al[3], baseA + CH_HALF + ra);
                uint32_t kb = ((uint32_t)(c * 8 + ks)) * 32 + bByte;
                uint32_t rb = sb + SM_W + bRow * 1040 + kb;
                ldm_x4(bh[0], bh[1], bh[2], bh[3], rb);
                ldm_x4(bl[0], bl[1], bl[2], bl[3], rb + WLO);
#pragma unroll
                for (int ni = 0; ni < 2; ni++) {
                    int o = ni * 2;
                    MMA_BF16(cf[ni], ah, bh[o], bh[o + 1]);
                    MMA_BF16(cf[ni], ah, bl[o], bl[o + 1]);
                    MMA_BF16(cf[ni], al, bh[o], bh[o + 1]);
                }
            }
        }

        // Dump fragments to sC[b][pr] (stride 36), stage xs
        {
            int r0 = wm + (lane >> 2);
#pragma unroll
            for (int ni = 0; ni < 2; ni++) {
                int col = wn + ni * 8 + (lane & 3) * 2;
                *(float2*)&sC[r0 * 36 + col]       = make_float2(cf[ni][0], cf[ni][1]);
                *(float2*)&sC[(r0 + 8) * 36 + col] = make_float2(cf[ni][2], cf[ni][3]);
            }
            int f0 = tid, f1 = tid + 256;
            *(float4*)&xs[(f0 >> 3) * 36 + (f0 & 7) * 4] = xr[0];
            *(float4*)&xs[(f1 >> 3) * 36 + (f1 & 7) * 4] = xr[1];
        }
        __syncthreads();

        // LSTM cells: 2 per thread (b = cb, hh = ch0 and ch0+4)
        char* hout = (char*)(hbase + (size_t)((t + 1) & 1) * HA_SZ + (size_t)chunk * CH_SZ);
#pragma unroll
        for (int cc = 0; cc < 2; cc++) {
            int hh = ch0 + cc * 4;
            int base = cb * 36 + hh * 4;
            float gi = sC[base + 0] + xs[base + 0];
            float gf = sC[base + 1] + xs[base + 1];
            float gg = sC[base + 2] + xs[base + 2];
            float go = sC[base + 3] + xs[base + 3];

            float si = sig_(gi);
            float sf = sig_(gf);
            float so = sig_(go);
            float tg = 2.f * sig_(2.f * gg) - 1.f;
            float c2 = sf * cst[cc] + si * tg;
            float tc = 2.f * sig_(2.f * c2) - 1.f;
            float hn = so * tc * mreg;
            cst[cc] = c2 * mreg;

            __nv_bfloat16 hb = __float2bfloat16(hn);
            __nv_bfloat16 lb = __float2bfloat16(hn - __bfloat162float(hb));
            int kloc = kloc0 + cc * 4;
            *(__nv_bfloat16*)(hout + cb * 272 + kloc * 2) = hb;
            *(__nv_bfloat16*)(hout + CH_HALF + cb * 272 + kloc * 2) = lb;
            outp[((size_t)tt * BB + cb) * (2 * HH) + dir * HH + blk * 8 + hh] = hn;
        }

        // Per-dir global barrier
        __threadfence();
        __syncthreads();
        if (tid == 0) {
            atomicAdd(bar, 1u);
            unsigned target = (unsigned)(t + 1) * 64u;
            unsigned v;
            do {
                asm volatile("ld.acquire.gpu.u32 %0, [%1];" : "=r"(v) : "l"(bar) : "memory");
            } while (v < target);
        }
        __syncthreads();
    }
}

// ---------------------------------------------------------------------------
// kernel_launch
// ---------------------------------------------------------------------------
extern "C" void kernel_launch(void* const* d_in, const int* in_sizes, int n_in,
                              void* d_out, int out_size)
{
    const float* x    = (const float*)d_in[0];
    const int*   mask = (const int*)  d_in[1];
    const float* w_ih = (const float*)d_in[2];
    const float* w_hh = (const float*)d_in[3];
    const float* b_ih = (const float*)d_in[4];
    const float* b_hh = (const float*)d_in[5];
    float* out = (float*)d_out;

    float* buf0 = nullptr;
    cudaGetSymbolAddress((void**)&buf0, g_buf0);
    __nv_bfloat16 *pAh, *pAl, *pWh, *pWl;
    cudaGetSymbolAddress((void**)&pAh, g_Ahi);
    cudaGetSymbolAddress((void**)&pAl, g_Alo);
    cudaGetSymbolAddress((void**)&pWh, g_Whi);
    cudaGetSymbolAddress((void**)&pWl, g_Wlo);

    cudaFuncSetAttribute(lstm_mma,
                         cudaFuncAttributeMaxDynamicSharedMemorySize, SMEM_LSTM);
    cudaFuncSetAttribute(proj_mma,
                         cudaFuncAttributeMaxDynamicSharedMemorySize, SMEM_PROJ);

    dim3 gproj(128, 32);
    dim3 gpers(64, 2);

    for (int layer = 0; layer < 2; layer++) {
        const float* inp  = (layer == 0) ? x : buf0;
        float*       outl = (layer == 1) ? out : buf0;

        pack_bf16<<<8192, 256>>>(inp, pAh, pAl);
        pack_bf16<<<2048, 256>>>(w_ih + (size_t)layer * 2 * FOURH * KP, pWh, pWl);
        pack_Wr<<<128, 256>>>(w_hh + (size_t)layer * 2 * FOURH * HH);
        zero_state<<<136, 256>>>();

        proj_mma<<<gproj, 256, SMEM_PROJ>>>(
            pAh, pAl, pWh, pWl,
            b_ih + (size_t)layer * 2 * FOURH,
            b_hh + (size_t)layer * 2 * FOURH);

        lstm_mma<<<gpers, 256, SMEM_LSTM>>>(mask, outl);
    }
}

// round 7
// speedup vs baseline: 3.3129x; 1.0973x over previous
#include <cuda_runtime.h>
#include <cuda_bf16.h>
#include <math.h>
#include <stdint.h>

// Problem constants
#define TT     256
#define BB     64
#define HH     512
#define FOURH  2048
#define KP     1024
#define MM     (TT*BB)     // 16384

// ---------------------------------------------------------------------------
// Device scratch (static only)
// ---------------------------------------------------------------------------
__device__ float g_xproj[(size_t)2*MM*FOURH];        // input projections, pr-packed cols
__device__ unsigned g_gbar[2];                       // per-dir step barrier counter

// proj operands: bf16 split, row-major. Layer-1 A is written by lstm_mma.
__device__ __align__(16) __nv_bfloat16 g_Ahi[(size_t)MM*KP];
__device__ __align__(16) __nv_bfloat16 g_Alo[(size_t)MM*KP];
__device__ __align__(16) __nv_bfloat16 g_Whi[(size_t)4096*KP];
__device__ __align__(16) __nv_bfloat16 g_Wlo[(size_t)4096*KP];

// recurrence W_hh: per (dir, block) slab: hi[32][1040B] + lo[32][1040B]
#define WSLAB 66560
#define WLO   33280
__device__ __align__(128) char g_Wr[(size_t)2*64*WSLAB];

// recurrence h state: [dir][ping][chunk4]{ hi[64][272B], lo[64][272B] }
#define CH_HALF 17408
#define CH_SZ   34816
#define HA_SZ   (4*CH_SZ)    // 139264 per (dir,ping)
__device__ __align__(128) char g_hA[(size_t)2*2*HA_SZ];

// ---------------------------------------------------------------------------
// PTX helpers
// ---------------------------------------------------------------------------
__device__ __forceinline__ uint32_t smem_u32(const void* p) {
    uint32_t a;
    asm("{ .reg .u64 t; cvta.to.shared.u64 t, %1; cvt.u32.u64 %0, t; }" : "=r"(a) : "l"(p));
    return a;
}
__device__ __forceinline__ void mbar_init(uint32_t mb, uint32_t cnt) {
    asm volatile("mbarrier.init.shared.b64 [%0], %1;" :: "r"(mb), "r"(cnt) : "memory");
}
__device__ __forceinline__ void mbar_expect_tx(uint32_t mb, uint32_t bytes) {
    asm volatile("mbarrier.arrive.expect_tx.shared.b64 _, [%0], %1;" :: "r"(mb), "r"(bytes) : "memory");
}
__device__ __forceinline__ void bulk_g2s(uint32_t dst, const void* src, uint32_t bytes, uint32_t mb) {
    asm volatile("cp.async.bulk.shared::cta.global.mbarrier::complete_tx::bytes [%0], [%1], %2, [%3];"
                 :: "r"(dst), "l"(src), "r"(bytes), "r"(mb) : "memory");
}
__device__ __forceinline__ void mbar_wait(uint32_t mb, uint32_t parity) {
    uint32_t done;
    asm volatile("{\n\t.reg .pred p;\n\t"
        "mbarrier.try_wait.parity.acquire.cta.shared::cta.b64 p, [%1], %2;\n\t"
        "selp.b32 %0, 1, 0, p;\n\t}"
        : "=r"(done) : "r"(mb), "r"(parity) : "memory");
    while (!done) {
        asm volatile("{\n\t.reg .pred p;\n\t"
            "mbarrier.try_wait.parity.acquire.cta.shared::cta.b64 p, [%1], %2, 0x989680;\n\t"
            "selp.b32 %0, 1, 0, p;\n\t}"
            : "=r"(done) : "r"(mb), "r"(parity) : "memory");
    }
}
__device__ __forceinline__ void cpa16(uint32_t dst, const void* src) {
    asm volatile("cp.async.cg.shared.global [%0], [%1], 16;" :: "r"(dst), "l"(src) : "memory");
}
__device__ __forceinline__ void ldm_x4(uint32_t& r0, uint32_t& r1, uint32_t& r2, uint32_t& r3,
                                       uint32_t addr) {
    asm volatile("ldmatrix.sync.aligned.m8n8.x4.shared.b16 {%0,%1,%2,%3}, [%4];"
                 : "=r"(r0), "=r"(r1), "=r"(r2), "=r"(r3) : "r"(addr));
}
#define MMA_BF16(c, a, b0v, b1v) \
    asm volatile("mma.sync.aligned.m16n8k16.row.col.f32.bf16.bf16.f32 " \
        "{%0,%1,%2,%3}, {%4,%5,%6,%7}, {%8,%9}, {%0,%1,%2,%3};" \
        : "+f"((c)[0]), "+f"((c)[1]), "+f"((c)[2]), "+f"((c)[3]) \
        : "r"((a)[0]), "r"((a)[1]), "r"((a)[2]), "r"((a)[3]), "r"(b0v), "r"(b1v))

__device__ __forceinline__ float sig_(float x) {
    return __fdividef(1.f, 1.f + __expf(-x));
}
__device__ __forceinline__ uint32_t pack_hilo(float a, float b, uint32_t& lo) {
    __nv_bfloat16 h0 = __float2bfloat16(a);
    __nv_bfloat16 h1 = __float2bfloat16(b);
    __nv_bfloat16 l0 = __float2bfloat16(a - __bfloat162float(h0));
    __nv_bfloat16 l1 = __float2bfloat16(b - __bfloat162float(h1));
    lo = (uint32_t)__bfloat16_as_ushort(l0) | ((uint32_t)__bfloat16_as_ushort(l1) << 16);
    return (uint32_t)__bfloat16_as_ushort(h0) | ((uint32_t)__bfloat16_as_ushort(h1) << 16);
}

// ---------------------------------------------------------------------------
// Zero h slot 0 (both dirs) + barrier counters
// ---------------------------------------------------------------------------
__global__ void zero_state() {
    uint32_t i = blockIdx.x * 256 + threadIdx.x;
    float* p = (float*)g_hA;
    if (i < HA_SZ / 4) {
        p[i] = 0.f;                                  // dir0 ping0
        p[i + (2 * HA_SZ) / 4] = 0.f;                // dir1 ping0
    }
    if (i < 2) g_gbar[i] = 0u;
}

// ---------------------------------------------------------------------------
// Pack fp32 -> hi/lo bf16 (row-major, 8 elems/thread)
// ---------------------------------------------------------------------------
__global__ __launch_bounds__(256) void pack_bf16(
    const float* __restrict__ src,
    __nv_bfloat16* __restrict__ hi, __nv_bfloat16* __restrict__ lo)
{
    size_t i = ((size_t)blockIdx.x * 256 + threadIdx.x) * 8;
    float4 v0 = *(const float4*)(src + i);
    float4 v1 = *(const float4*)(src + i + 4);
    float xv[8] = {v0.x, v0.y, v0.z, v0.w, v1.x, v1.y, v1.z, v1.w};
    uint32_t hp[4], lp[4];
#pragma unroll
    for (int e = 0; e < 4; e++) hp[e] = pack_hilo(xv[2*e], xv[2*e+1], lp[e]);
    *(uint4*)(hi + i) = make_uint4(hp[0], hp[1], hp[2], hp[3]);
    *(uint4*)(lo + i) = make_uint4(lp[0], lp[1], lp[2], lp[3]);
}

// ---------------------------------------------------------------------------
// Pack W_hh into per-block slabs: row pr=hh*4+g  <-  W[g*512 + blk*8+hh][k]
// ---------------------------------------------------------------------------
__global__ __launch_bounds__(256) void pack_Wr(const float* __restrict__ whh) {
    const int dir = blockIdx.x >> 6, blk = blockIdx.x & 63;
    char* slab = g_Wr + (size_t)(dir * 64 + blk) * WSLAB;
    for (int i = threadIdx.x; i < 8192; i += 256) {
        int r = i >> 8;
        int k2 = (i & 255) * 2;
        int hh = r >> 2, g = r & 3;
        int grow = g * HH + blk * 8 + hh;
        float2 v = *(const float2*)&whh[((size_t)dir * FOURH + grow) * HH + k2];
        uint32_t lo, hi = pack_hilo(v.x, v.y, lo);
        *(uint32_t*)(slab + r * 1040 + k2 * 2) = hi;
        *(uint32_t*)(slab + WLO + r * 1040 + k2 * 2) = lo;
    }
}

// ---------------------------------------------------------------------------
// HMMA projection GEMM, 3-stage cp.async pipeline.
// CTA tile 128m x 128n x 64k, 256 threads (8 warps, 2m x 4n of 64x32).
// ---------------------------------------------------------------------------
#define ROWB   144
#define TILEB  (128*ROWB)
#define STGB   (4*TILEB)                  // 73728
#define OFF_BIAS (3*STGB)                 // 221184
#define SMEM_PROJ (OFF_BIAS + 768)

__global__ __launch_bounds__(256, 1) void proj_mma(
    const __nv_bfloat16* __restrict__ Ah, const __nv_bfloat16* __restrict__ Al,
    const __nv_bfloat16* __restrict__ Wh, const __nv_bfloat16* __restrict__ Wl,
    const float* __restrict__ b1, const float* __restrict__ b2)
{
    extern __shared__ __align__(128) char smp[];
    const uint32_t sb = smem_u32(smp);
    float* bias = (float*)(smp + OFF_BIAS);

    const int tid  = threadIdx.x;
    const int lane = tid & 31;
    const int w    = tid >> 5;
    const int m0   = blockIdx.x * 128;
    const int nG   = blockIdx.y * 128;
    const int dir  = nG >> 11;
    const int nd   = nG & 2047;
    const int wm   = (w >> 2) * 64;
    const int wn   = (w & 3) * 32;

    if (tid < 128) bias[tid] = b1[dir * FOURH + nd + tid] + b2[dir * FOURH + nd + tid];

    int cr[16], cc[16], ct[16];
#pragma unroll
    for (int i = 0; i < 16; i++) {
        int c = i * 256 + tid;
        ct[i] = c >> 10; cr[i] = (c >> 3) & 127; cc[i] = c & 7;
    }

    auto load_stage = [&](int s, int kt) {
        uint32_t base = sb + (uint32_t)s * STGB;
#pragma unroll
        for (int i = 0; i < 16; i++) {
            uint32_t dst = base + (uint32_t)ct[i] * TILEB + (uint32_t)cr[i] * ROWB + (uint32_t)cc[i] * 16;
            const __nv_bfloat16* g;
            if (ct[i] == 0)      g = Ah + (size_t)(m0 + cr[i]) * KP + kt * 64 + cc[i] * 8;
            else if (ct[i] == 1) g = Al + (size_t)(m0 + cr[i]) * KP + kt * 64 + cc[i] * 8;
            else if (ct[i] == 2) g = Wh + (size_t)(nG + cr[i]) * KP + kt * 64 + cc[i] * 8;
            else                 g = Wl + (size_t)(nG + cr[i]) * KP + kt * 64 + cc[i] * 8;
            cpa16(dst, g);
        }
        asm volatile("cp.async.commit_group;" ::: "memory");
    };

    float c[4][4][4];
#pragma unroll
    for (int mi = 0; mi < 4; mi++)
#pragma unroll
        for (int ni = 0; ni < 4; ni++)
#pragma unroll
            for (int j = 0; j < 4; j++) c[mi][ni][j] = 0.f;

    const uint32_t aRow  = (uint32_t)(wm + (lane & 15));
    const uint32_t aByte = (lane & 16) ? 16u : 0u;
    const uint32_t bRow  = (uint32_t)(wn + (lane & 7) + ((lane & 16) ? 8 : 0));
    const uint32_t bByte = (lane & 8) ? 16u : 0u;

    load_stage(0, 0);
    load_stage(1, 1);

    for (int kt = 0; kt < 16; kt++) {
        if (kt + 2 < 16) {
            load_stage((kt + 2) % 3, kt + 2);
            asm volatile("cp.async.wait_group 2;" ::: "memory");
        } else if (kt + 1 < 16) {
            asm volatile("cp.async.wait_group 1;" ::: "memory");
        } else {
            asm volatile("cp.async.wait_group 0;" ::: "memory");
        }
        __syncthreads();

        uint32_t st = sb + (uint32_t)(kt % 3) * STGB;
#pragma unroll
        for (int ks = 0; ks < 4; ks++) {
            uint32_t kb = (uint32_t)(ks * 32);
            uint32_t ah[4][4], al[4][4], bh[2][4], bl[2][4];
#pragma unroll
            for (int mi = 0; mi < 4; mi++) {
                uint32_t ra = (aRow + mi * 16) * ROWB + kb + aByte;
                ldm_x4(ah[mi][0], ah[mi][1], ah[mi][2], ah[mi][3], st + ra);
                ldm_x4(al[mi][0], al[mi][1], al[mi][2], al[mi][3], st + TILEB + ra);
            }
#pragma unroll
            for (int np = 0; np < 2; np++) {
                uint32_t rb = (bRow + np * 16) * ROWB + kb + bByte;
                ldm_x4(bh[np][0], bh[np][1], bh[np][2], bh[np][3], st + 2 * TILEB + rb);
                ldm_x4(bl[np][0], bl[np][1], bl[np][2], bl[np][3], st + 3 * TILEB + rb);
            }
#pragma unroll
            for (int mi = 0; mi < 4; mi++)
#pragma unroll
                for (int ni = 0; ni < 4; ni++) {
                    int np = ni >> 1, o = (ni & 1) * 2;
                    MMA_BF16(c[mi][ni], ah[mi], bh[np][o], bh[np][o + 1]);
                    MMA_BF16(c[mi][ni], ah[mi], bl[np][o], bl[np][o + 1]);
                    MMA_BF16(c[mi][ni], al[mi], bh[np][o], bh[np][o + 1]);
                }
        }
        __syncthreads();
    }

    // Epilogue: bias + scatter to pr-packed layout: pr = (n&511)*4 + (n>>9)
    float* outD = g_xproj + (size_t)dir * MM * FOURH;
#pragma unroll
    for (int mi = 0; mi < 4; mi++) {
        int row0 = m0 + wm + mi * 16 + (lane >> 2);
#pragma unroll
        for (int ni = 0; ni < 4; ni++) {
            int colL = wn + ni * 8 + (lane & 3) * 2;
            float bx = bias[colL], by = bias[colL + 1];
            int n0 = nd + colL;
            int pr0 = (n0 & 511) * 4 + (n0 >> 9);
            int pr1 = ((n0 + 1) & 511) * 4 + ((n0 + 1) >> 9);
            outD[(size_t)row0 * FOURH + pr0] = c[mi][ni][0] + bx;
            outD[(size_t)row0 * FOURH + pr1] = c[mi][ni][1] + by;
            outD[(size_t)(row0 + 8) * FOURH + pr0] = c[mi][ni][2] + bx;
            outD[(size_t)(row0 + 8) * FOURH + pr1] = c[mi][ni][3] + by;
        }
    }
}

// ---------------------------------------------------------------------------
// Persistent HMMA recurrence. grid = (64 blk, 2 dir), 256 threads (8 warps).
// mode 0: write packed bf16 A for next layer's proj. mode 1: write fp32 outp.
// ---------------------------------------------------------------------------
#define SM_A  0                         // 4 chunks x (hi 17408 + lo 17408)
#define SM_W  139264                    // hi[32][1040] + lo[32][1040]
#define SM_C  205824                    // sC[64][36] fp32
#define SM_X  215040                    // xs[64][36] fp32 (reused as staging)
#define SM_MB 224256                    // 5 mbarriers
#define SMEM_LSTM 224320

__global__ __launch_bounds__(256, 1) void lstm_mma(
    const int* __restrict__ mask,     // [B][T]
    float*     __restrict__ outp,     // [T][B][2H] (mode 1)
    int mode)
{
    extern __shared__ __align__(128) char sm[];
    const uint32_t sb = smem_u32(sm);
    float* sC = (float*)(sm + SM_C);
    float* xs = (float*)(sm + SM_X);

    const int dir = blockIdx.y;
    const int blk = blockIdx.x;
    const int tid = threadIdx.x;
    const int lane = tid & 31;
    const int w = tid >> 5;
    const int wm = (w >> 1) * 16;
    const int wn = (w & 1) * 16;

    const uint32_t mb0 = sb + SM_MB;
    if (tid == 0) {
        for (int c = 0; c < 5; c++) mbar_init(mb0 + c * 8, 1);
        asm volatile("fence.proxy.async.shared::cta;" ::: "memory");
        mbar_expect_tx(mb0 + 32, (uint32_t)WSLAB);
        bulk_g2s(sb + SM_W, g_Wr + (size_t)(dir * 64 + blk) * WSLAB, (uint32_t)WSLAB, mb0 + 32);
    }
    __syncthreads();
    mbar_wait(mb0 + 32, 0);

    const uint32_t aRow  = (uint32_t)(wm + (lane & 15));
    const uint32_t aByte = (lane & 16) ? 16u : 0u;
    const uint32_t bRow  = (uint32_t)(wn + (lane & 7) + ((lane & 16) ? 8 : 0));
    const uint32_t bByte = (lane & 8) ? 16u : 0u;

    const float* xprjD = g_xproj + (size_t)dir * MM * FOURH;
    unsigned* bar = &g_gbar[dir];
    const char* hbase = g_hA + (size_t)dir * 2 * HA_SZ;

    const int cb  = tid & 63;
    const int ch0 = tid >> 6;           // 0..3
    const int chunk = blk >> 4;
    const uint32_t klocByte = (uint32_t)((blk & 15) * 16);
    float cst[2] = {0.f, 0.f};

    for (int t = 0; t < TT; t++) {
        const int tt = dir ? (TT - 1 - t) : t;

        if (tid == 0) {
            asm volatile("fence.proxy.async.shared::cta;" ::: "memory");
            const char* src = hbase + (size_t)(t & 1) * HA_SZ;
#pragma unroll
            for (int c = 0; c < 4; c++) {
                mbar_expect_tx(mb0 + c * 8, (uint32_t)CH_SZ);
                bulk_g2s(sb + SM_A + c * CH_SZ, src + c * CH_SZ, (uint32_t)CH_SZ, mb0 + c * 8);
            }
        }

        // Prefetch xproj slice + mask
        float4 xr[2];
        {
            int f0 = tid, f1 = tid + 256;
            xr[0] = *(const float4*)&xprjD[((size_t)tt * BB + (f0 >> 3)) * FOURH + blk * 32 + (f0 & 7) * 4];
            xr[1] = *(const float4*)&xprjD[((size_t)tt * BB + (f1 >> 3)) * FOURH + blk * 32 + (f1 & 7) * 4];
        }
        const float mreg = (float)mask[cb * TT + tt];

        // MMA: C[64b x 32pr] = h[64x512] . Wslice^T (split bf16)
        float cf[2][4];
#pragma unroll
        for (int ni = 0; ni < 2; ni++)
#pragma unroll
            for (int j = 0; j < 4; j++) cf[ni][j] = 0.f;

        const uint32_t par = (uint32_t)(t & 1);
#pragma unroll
        for (int c = 0; c < 4; c++) {
            mbar_wait(mb0 + c * 8, par);
            uint32_t baseA = sb + SM_A + (uint32_t)c * CH_SZ;
#pragma unroll
            for (int ks = 0; ks < 8; ks++) {
                uint32_t ah[4], al[4], bh[4], bl[4];
                uint32_t ra = aRow * 272 + (uint32_t)ks * 32 + aByte;
                ldm_x4(ah[0], ah[1], ah[2], ah[3], baseA + ra);
                ldm_x4(al[0], al[1], al[2], al[3], baseA + CH_HALF + ra);
                uint32_t kb = ((uint32_t)(c * 8 + ks)) * 32 + bByte;
                uint32_t rb = sb + SM_W + bRow * 1040 + kb;
                ldm_x4(bh[0], bh[1], bh[2], bh[3], rb);
                ldm_x4(bl[0], bl[1], bl[2], bl[3], rb + WLO);
#pragma unroll
                for (int ni = 0; ni < 2; ni++) {
                    int o = ni * 2;
                    MMA_BF16(cf[ni], ah, bh[o], bh[o + 1]);
                    MMA_BF16(cf[ni], ah, bl[o], bl[o + 1]);
                    MMA_BF16(cf[ni], al, bh[o], bh[o + 1]);
                }
            }
        }

        // Dump fragments to sC[b][pr] (stride 36), stage xs
        {
            int r0 = wm + (lane >> 2);
#pragma unroll
            for (int ni = 0; ni < 2; ni++) {
                int col = wn + ni * 8 + (lane & 3) * 2;
                *(float2*)&sC[r0 * 36 + col]       = make_float2(cf[ni][0], cf[ni][1]);
                *(float2*)&sC[(r0 + 8) * 36 + col] = make_float2(cf[ni][2], cf[ni][3]);
            }
            int f0 = tid, f1 = tid + 256;
            *(float4*)&xs[(f0 >> 3) * 36 + (f0 & 7) * 4] = xr[0];
            *(float4*)&xs[(f1 >> 3) * 36 + (f1 & 7) * 4] = xr[1];
        }
        __syncthreads();

        // LSTM cells: 2 per thread (b = cb, hh = ch0, ch0+4)
        float hnv[2];
#pragma unroll
        for (int cc = 0; cc < 2; cc++) {
            int hh = ch0 + cc * 4;
            int base = cb * 36 + hh * 4;
            float gi = sC[base + 0] + xs[base + 0];
            float gf = sC[base + 1] + xs[base + 1];
            float gg = sC[base + 2] + xs[base + 2];
            float go = sC[base + 3] + xs[base + 3];

            float si = sig_(gi);
            float sf = sig_(gf);
            float so = sig_(go);
            float tg = 2.f * sig_(2.f * gg) - 1.f;
            float c2 = sf * cst[cc] + si * tg;
            float tc = 2.f * sig_(2.f * c2) - 1.f;
            float hn = so * tc * mreg;
            cst[cc] = c2 * mreg;
            hnv[cc] = hn;
        }
        __syncthreads();   // all xs/sC reads done before staging overwrite

        // Stage into xs region: sHhi[0,1024)B, sHlo[1024,2048)B, sF32[2048,4096)B
        {
            uint16_t* sHhi = (uint16_t*)xs;
            uint16_t* sHlo = (uint16_t*)xs + 512;
            float*    sF32 = xs + 512;
#pragma unroll
            for (int cc = 0; cc < 2; cc++) {
                int hh = ch0 + cc * 4;
                float hn = hnv[cc];
                __nv_bfloat16 hb = __float2bfloat16(hn);
                __nv_bfloat16 lb = __float2bfloat16(hn - __bfloat162float(hb));
                sHhi[cb * 8 + hh] = __bfloat16_as_ushort(hb);
                sHlo[cb * 8 + hh] = __bfloat16_as_ushort(lb);
                if (mode) sF32[cb * 8 + hh] = hn;
            }
        }
        __syncthreads();

        // Coalesced 16B stores
        char* hout = (char*)(hbase + (size_t)((t + 1) & 1) * HA_SZ + (size_t)chunk * CH_SZ);
        if (tid < 64) {
            uint4 v = *(uint4*)((char*)xs + tid * 16);
            *(uint4*)(hout + tid * 272 + klocByte) = v;
        } else if (tid < 128) {
            int r = tid - 64;
            uint4 v = *(uint4*)((char*)xs + 1024 + r * 16);
            *(uint4*)(hout + CH_HALF + r * 272 + klocByte) = v;
        } else if (mode == 0) {
            if (tid < 192) {
                int r = tid - 128;
                uint4 v = *(uint4*)((char*)xs + r * 16);
                *(uint4*)((char*)g_Ahi + ((size_t)(tt * 64 + r) * 1024 + dir * 512 + blk * 8) * 2) = v;
            } else {
                int r = tid - 192;
                uint4 v = *(uint4*)((char*)xs + 1024 + r * 16);
                *(uint4*)((char*)g_Alo + ((size_t)(tt * 64 + r) * 1024 + dir * 512 + blk * 8) * 2) = v;
            }
        } else {
            int r = (tid - 128) >> 1, half = tid & 1;
            float4 v = *(float4*)((char*)xs + 2048 + r * 32 + half * 16);
            *(float4*)&outp[((size_t)tt * 64 + r) * 1024 + dir * 512 + blk * 8 + half * 4] = v;
        }

        // Per-dir global barrier
        __threadfence();
        __syncthreads();
        if (tid == 0) {
            atomicAdd(bar, 1u);
            unsigned target = (unsigned)(t + 1) * 64u;
            unsigned v;
            do {
                asm volatile("ld.acquire.gpu.u32 %0, [%1];" : "=r"(v) : "l"(bar) : "memory");
            } while (v < target);
        }
        __syncthreads();
    }
}

// ---------------------------------------------------------------------------
// kernel_launch
// ---------------------------------------------------------------------------
extern "C" void kernel_launch(void* const* d_in, const int* in_sizes, int n_in,
                              void* d_out, int out_size)
{
    const float* x    = (const float*)d_in[0];
    const int*   mask = (const int*)  d_in[1];
    const float* w_ih = (const float*)d_in[2];
    const float* w_hh = (const float*)d_in[3];
    const float* b_ih = (const float*)d_in[4];
    const float* b_hh = (const float*)d_in[5];
    float* out = (float*)d_out;

    __nv_bfloat16 *pAh, *pAl, *pWh, *pWl;
    cudaGetSymbolAddress((void**)&pAh, g_Ahi);
    cudaGetSymbolAddress((void**)&pAl, g_Alo);
    cudaGetSymbolAddress((void**)&pWh, g_Whi);
    cudaGetSymbolAddress((void**)&pWl, g_Wlo);

    cudaFuncSetAttribute(lstm_mma,
                         cudaFuncAttributeMaxDynamicSharedMemorySize, SMEM_LSTM);
    cudaFuncSetAttribute(proj_mma,
                         cudaFuncAttributeMaxDynamicSharedMemorySize, SMEM_PROJ);

    dim3 gproj(128, 32);
    dim3 gpers(64, 2);

    for (int layer = 0; layer < 2; layer++) {
        if (layer == 0) pack_bf16<<<8192, 256>>>(x, pAh, pAl);
        // layer 1: g_Ahi/g_Alo already written by layer-0 lstm_mma

        pack_bf16<<<2048, 256>>>(w_ih + (size_t)layer * 2 * FOURH * KP, pWh, pWl);
        pack_Wr<<<128, 256>>>(w_hh + (size_t)layer * 2 * FOURH * HH);
        zero_state<<<136, 256>>>();

        proj_mma<<<gproj, 256, SMEM_PROJ>>>(
            pAh, pAl, pWh, pWl,
            b_ih + (size_t)layer * 2 * FOURH,
            b_hh + (size_t)layer * 2 * FOURH);

        lstm_mma<<<gpers, 256, SMEM_LSTM>>>(mask, (layer == 1) ? out : nullptr, layer);
    }
}

// round 8
// speedup vs baseline: 3.8752x; 1.1697x over previous
#include <cuda_runtime.h>
#include <cuda_bf16.h>
#include <math.h>
#include <stdint.h>

// Problem constants
#define TT     256
#define BB     64
#define HH     512
#define FOURH  2048
#define KP     1024
#define MM     (TT*BB)     // 16384

// ---------------------------------------------------------------------------
// Device scratch (static only)
// ---------------------------------------------------------------------------
__device__ float g_xproj[(size_t)2*MM*FOURH];        // input projections, pr-packed cols
__device__ unsigned g_gbar[2];                       // per-dir step barrier counter

// proj operands: bf16 split, row-major. Layer-1 A is written by lstm_mma.
__device__ __align__(16) __nv_bfloat16 g_Ahi[(size_t)MM*KP];
__device__ __align__(16) __nv_bfloat16 g_Alo[(size_t)MM*KP];
__device__ __align__(16) __nv_bfloat16 g_Whi[(size_t)4096*KP];
__device__ __align__(16) __nv_bfloat16 g_Wlo[(size_t)4096*KP];

// recurrence W_hh: per (dir, block) slab: hi[32][1040B] + lo[32][1040B]
#define WSLAB 66560
#define WLO   33280
__device__ __align__(128) char g_Wr[(size_t)2*64*WSLAB];

// recurrence h state: [dir][ping][chunk4]{ hi[64][272B], lo[64][272B] }
#define CH_HALF 17408
#define CH_SZ   34816
#define HA_SZ   (4*CH_SZ)    // 139264 per (dir,ping)
__device__ __align__(128) char g_hA[(size_t)2*2*HA_SZ];

// ---------------------------------------------------------------------------
// PTX helpers
// ---------------------------------------------------------------------------
__device__ __forceinline__ uint32_t smem_u32(const void* p) {
    uint32_t a;
    asm("{ .reg .u64 t; cvta.to.shared.u64 t, %1; cvt.u32.u64 %0, t; }" : "=r"(a) : "l"(p));
    return a;
}
__device__ __forceinline__ void mbar_init(uint32_t mb, uint32_t cnt) {
    asm volatile("mbarrier.init.shared.b64 [%0], %1;" :: "r"(mb), "r"(cnt) : "memory");
}
__device__ __forceinline__ void mbar_expect_tx(uint32_t mb, uint32_t bytes) {
    asm volatile("mbarrier.arrive.expect_tx.shared.b64 _, [%0], %1;" :: "r"(mb), "r"(bytes) : "memory");
}
__device__ __forceinline__ void bulk_g2s(uint32_t dst, const void* src, uint32_t bytes, uint32_t mb) {
    asm volatile("cp.async.bulk.shared::cta.global.mbarrier::complete_tx::bytes [%0], [%1], %2, [%3];"
                 :: "r"(dst), "l"(src), "r"(bytes), "r"(mb) : "memory");
}
__device__ __forceinline__ void mbar_wait(uint32_t mb, uint32_t parity) {
    uint32_t done;
    asm volatile("{\n\t.reg .pred p;\n\t"
        "mbarrier.try_wait.parity.acquire.cta.shared::cta.b64 p, [%1], %2;\n\t"
        "selp.b32 %0, 1, 0, p;\n\t}"
        : "=r"(done) : "r"(mb), "r"(parity) : "memory");
    while (!done) {
        asm volatile("{\n\t.reg .pred p;\n\t"
            "mbarrier.try_wait.parity.acquire.cta.shared::cta.b64 p, [%1], %2, 0x989680;\n\t"
            "selp.b32 %0, 1, 0, p;\n\t}"
            : "=r"(done) : "r"(mb), "r"(parity) : "memory");
    }
}
__device__ __forceinline__ void cpa16(uint32_t dst, const void* src) {
    asm volatile("cp.async.cg.shared.global [%0], [%1], 16;" :: "r"(dst), "l"(src) : "memory");
}
__device__ __forceinline__ void ldm_x4(uint32_t& r0, uint32_t& r1, uint32_t& r2, uint32_t& r3,
                                       uint32_t addr) {
    asm volatile("ldmatrix.sync.aligned.m8n8.x4.shared.b16 {%0,%1,%2,%3}, [%4];"
                 : "=r"(r0), "=r"(r1), "=r"(r2), "=r"(r3) : "r"(addr));
}
#define MMA_BF16(c, a, b0v, b1v) \
    asm volatile("mma.sync.aligned.m16n8k16.row.col.f32.bf16.bf16.f32 " \
        "{%0,%1,%2,%3}, {%4,%5,%6,%7}, {%8,%9}, {%0,%1,%2,%3};" \
        : "+f"((c)[0]), "+f"((c)[1]), "+f"((c)[2]), "+f"((c)[3]) \
        : "r"((a)[0]), "r"((a)[1]), "r"((a)[2]), "r"((a)[3]), "r"(b0v), "r"(b1v))

__device__ __forceinline__ float sig_(float x) {
    return __fdividef(1.f, 1.f + __expf(-x));
}
__device__ __forceinline__ uint32_t pack_hilo(float a, float b, uint32_t& lo) {
    __nv_bfloat16 h0 = __float2bfloat16(a);
    __nv_bfloat16 h1 = __float2bfloat16(b);
    __nv_bfloat16 l0 = __float2bfloat16(a - __bfloat162float(h0));
    __nv_bfloat16 l1 = __float2bfloat16(b - __bfloat162float(h1));
    lo = (uint32_t)__bfloat16_as_ushort(l0) | ((uint32_t)__bfloat16_as_ushort(l1) << 16);
    return (uint32_t)__bfloat16_as_ushort(h0) | ((uint32_t)__bfloat16_as_ushort(h1) << 16);
}

// ---------------------------------------------------------------------------
// Zero h slot 0 (both dirs) + barrier counters
// ---------------------------------------------------------------------------
__global__ void zero_state() {
    uint32_t i = blockIdx.x * 256 + threadIdx.x;
    float* p = (float*)g_hA;
    if (i < HA_SZ / 4) {
        p[i] = 0.f;
        p[i + (2 * HA_SZ) / 4] = 0.f;
    }
    if (i < 2) g_gbar[i] = 0u;
}

// ---------------------------------------------------------------------------
// Pack fp32 -> hi/lo bf16 (row-major, 8 elems/thread)
// ---------------------------------------------------------------------------
__global__ __launch_bounds__(256) void pack_bf16(
    const float* __restrict__ src,
    __nv_bfloat16* __restrict__ hi, __nv_bfloat16* __restrict__ lo)
{
    size_t i = ((size_t)blockIdx.x * 256 + threadIdx.x) * 8;
    float4 v0 = *(const float4*)(src + i);
    float4 v1 = *(const float4*)(src + i + 4);
    float xv[8] = {v0.x, v0.y, v0.z, v0.w, v1.x, v1.y, v1.z, v1.w};
    uint32_t hp[4], lp[4];
#pragma unroll
    for (int e = 0; e < 4; e++) hp[e] = pack_hilo(xv[2*e], xv[2*e+1], lp[e]);
    *(uint4*)(hi + i) = make_uint4(hp[0], hp[1], hp[2], hp[3]);
    *(uint4*)(lo + i) = make_uint4(lp[0], lp[1], lp[2], lp[3]);
}

// ---------------------------------------------------------------------------
// Pack W_hh into per-block slabs: row pr=hh*4+g  <-  W[g*512 + blk*8+hh][k]
// ---------------------------------------------------------------------------
__global__ __launch_bounds__(256) void pack_Wr(const float* __restrict__ whh) {
    const int dir = blockIdx.x >> 6, blk = blockIdx.x & 63;
    char* slab = g_Wr + (size_t)(dir * 64 + blk) * WSLAB;
    for (int i = threadIdx.x; i < 8192; i += 256) {
        int r = i >> 8;
        int k2 = (i & 255) * 2;
        int hh = r >> 2, g = r & 3;
        int grow = g * HH + blk * 8 + hh;
        float2 v = *(const float2*)&whh[((size_t)dir * FOURH + grow) * HH + k2];
        uint32_t lo, hi = pack_hilo(v.x, v.y, lo);
        *(uint32_t*)(slab + r * 1040 + k2 * 2) = hi;
        *(uint32_t*)(slab + WLO + r * 1040 + k2 * 2) = lo;
    }
}

// ---------------------------------------------------------------------------
// HMMA projection GEMM, 3-stage pipeline, CTA tile = 128 rows x 128 PR-cols.
// pr = hh*4+g; W natural row for pr: n = (pr&3)*512 + (pr>>2).
// Epilogue stores are consecutive in pr -> fully coalesced.
// ---------------------------------------------------------------------------
#define ROWB   144
#define TILEB  (128*ROWB)
#define STGB   (4*TILEB)                  // 73728
#define OFF_BIAS (3*STGB)                 // 221184
#define SMEM_PROJ (OFF_BIAS + 768)

__global__ __launch_bounds__(256, 1) void proj_mma(
    const __nv_bfloat16* __restrict__ Ah, const __nv_bfloat16* __restrict__ Al,
    const __nv_bfloat16* __restrict__ Wh, const __nv_bfloat16* __restrict__ Wl,
    const float* __restrict__ b1, const float* __restrict__ b2)
{
    extern __shared__ __align__(128) char smp[];
    const uint32_t sb = smem_u32(smp);
    float* bias = (float*)(smp + OFF_BIAS);

    const int tid  = threadIdx.x;
    const int lane = tid & 31;
    const int w    = tid >> 5;
    const int m0   = blockIdx.x * 128;
    const int dir  = blockIdx.y >> 4;
    const int prG  = (blockIdx.y & 15) * 128;   // pr-block base within dir
    const int prB  = prG >> 2;                  // habs base (pr>>2)
    const int wm   = (w >> 2) * 64;
    const int wn   = (w & 3) * 32;

    if (tid < 128) {
        int n = (tid & 3) * 512 + prB + (tid >> 2);   // natural col for pr = prG+tid
        bias[tid] = b1[dir * FOURH + n] + b2[dir * FOURH + n];
    }

    int cr[16], cc[16], ct[16];
#pragma unroll
    for (int i = 0; i < 16; i++) {
        int c = i * 256 + tid;
        ct[i] = c >> 10; cr[i] = (c >> 3) & 127; cc[i] = c & 7;
    }

    auto load_stage = [&](int s, int kt) {
        uint32_t base = sb + (uint32_t)s * STGB;
#pragma unroll
        for (int i = 0; i < 16; i++) {
            uint32_t dst = base + (uint32_t)ct[i] * TILEB + (uint32_t)cr[i] * ROWB + (uint32_t)cc[i] * 16;
            const __nv_bfloat16* g;
            if (ct[i] == 0)      g = Ah + (size_t)(m0 + cr[i]) * KP + kt * 64 + cc[i] * 8;
            else if (ct[i] == 1) g = Al + (size_t)(m0 + cr[i]) * KP + kt * 64 + cc[i] * 8;
            else {
                int n = (cr[i] & 3) * 512 + prB + (cr[i] >> 2);   // pr -> natural row
                const __nv_bfloat16* Wb = (ct[i] == 2) ? Wh : Wl;
                g = Wb + (size_t)(dir * FOURH + n) * KP + kt * 64 + cc[i] * 8;
            }
            cpa16(dst, g);
        }
        asm volatile("cp.async.commit_group;" ::: "memory");
    };

    float c[4][4][4];
#pragma unroll
    for (int mi = 0; mi < 4; mi++)
#pragma unroll
        for (int ni = 0; ni < 4; ni++)
#pragma unroll
            for (int j = 0; j < 4; j++) c[mi][ni][j] = 0.f;

    const uint32_t aRow  = (uint32_t)(wm + (lane & 15));
    const uint32_t aByte = (lane & 16) ? 16u : 0u;
    const uint32_t bRow  = (uint32_t)(wn + (lane & 7) + ((lane & 16) ? 8 : 0));
    const uint32_t bByte = (lane & 8) ? 16u : 0u;

    load_stage(0, 0);
    load_stage(1, 1);

    for (int kt = 0; kt < 16; kt++) {
        if (kt + 2 < 16) {
            load_stage((kt + 2) % 3, kt + 2);
            asm volatile("cp.async.wait_group 2;" ::: "memory");
        } else if (kt + 1 < 16) {
            asm volatile("cp.async.wait_group 1;" ::: "memory");
        } else {
            asm volatile("cp.async.wait_group 0;" ::: "memory");
        }
        __syncthreads();

        uint32_t st = sb + (uint32_t)(kt % 3) * STGB;
#pragma unroll
        for (int ks = 0; ks < 4; ks++) {
            uint32_t kb = (uint32_t)(ks * 32);
            uint32_t ah[4][4], al[4][4], bh[2][4], bl[2][4];
#pragma unroll
            for (int mi = 0; mi < 4; mi++) {
                uint32_t ra = (aRow + mi * 16) * ROWB + kb + aByte;
                ldm_x4(ah[mi][0], ah[mi][1], ah[mi][2], ah[mi][3], st + ra);
                ldm_x4(al[mi][0], al[mi][1], al[mi][2], al[mi][3], st + TILEB + ra);
            }
#pragma unroll
            for (int np = 0; np < 2; np++) {
                uint32_t rb = (bRow + np * 16) * ROWB + kb + bByte;
                ldm_x4(bh[np][0], bh[np][1], bh[np][2], bh[np][3], st + 2 * TILEB + rb);
                ldm_x4(bl[np][0], bl[np][1], bl[np][2], bl[np][3], st + 3 * TILEB + rb);
            }
#pragma unroll
            for (int mi = 0; mi < 4; mi++)
#pragma unroll
                for (int ni = 0; ni < 4; ni++) {
                    int np = ni >> 1, o = (ni & 1) * 2;
                    MMA_BF16(c[mi][ni], ah[mi], bh[np][o], bh[np][o + 1]);
                    MMA_BF16(c[mi][ni], ah[mi], bl[np][o], bl[np][o + 1]);
                    MMA_BF16(c[mi][ni], al[mi], bh[np][o], bh[np][o + 1]);
                }
        }
        __syncthreads();
    }

    // Epilogue: bias + consecutive float2 stores (pr-contiguous)
    float* outD = g_xproj + (size_t)dir * MM * FOURH;
#pragma unroll
    for (int mi = 0; mi < 4; mi++) {
        int row0 = m0 + wm + mi * 16 + (lane >> 2);
#pragma unroll
        for (int ni = 0; ni < 4; ni++) {
            int colL = wn + ni * 8 + (lane & 3) * 2;
            float bx = bias[colL], by = bias[colL + 1];
            *(float2*)&outD[(size_t)row0 * FOURH + prG + colL] =
                make_float2(c[mi][ni][0] + bx, c[mi][ni][1] + by);
            *(float2*)&outD[(size_t)(row0 + 8) * FOURH + prG + colL] =
                make_float2(c[mi][ni][2] + bx, c[mi][ni][3] + by);
        }
    }
}

// ---------------------------------------------------------------------------
// Persistent HMMA recurrence. grid = (64 blk, 2 dir), 256 threads (8 warps).
// Fragment-direct epilogue: xproj added to fragments, gates exchanged via
// shfl_xor(1), cells computed in registers. 3 syncthreads per step.
// ---------------------------------------------------------------------------
#define SM_A  0                         // 4 chunks x (hi 17408 + lo 17408)
#define SM_W  139264                    // hi[32][1040] + lo[32][1040]
#define SM_ST 205824                    // staging: hi 1KB | lo 1KB | f32 2KB
#define SM_MB 209920                    // 5 mbarriers
#define SMEM_LSTM 209984

__global__ __launch_bounds__(256, 1) void lstm_mma(
    const int* __restrict__ mask,     // [B][T]
    float*     __restrict__ outp,     // [T][B][2H] (mode 1)
    int mode)
{
    extern __shared__ __align__(128) char sm[];
    const uint32_t sb = smem_u32(sm);
    uint16_t* sHhi = (uint16_t*)(sm + SM_ST);
    uint16_t* sHlo = (uint16_t*)(sm + SM_ST + 1024);
    float*    sF32 = (float*)(sm + SM_ST + 2048);

    const int dir = blockIdx.y;
    const int blk = blockIdx.x;
    const int tid = threadIdx.x;
    const int lane = tid & 31;
    const int w = tid >> 5;
    const int wm = (w >> 1) * 16;       // batch offset
    const int wn = (w & 1) * 16;        // pr offset

    const uint32_t mb0 = sb + SM_MB;
    if (tid == 0) {
        for (int c = 0; c < 5; c++) mbar_init(mb0 + c * 8, 1);
        asm volatile("fence.proxy.async.shared::cta;" ::: "memory");
        mbar_expect_tx(mb0 + 32, (uint32_t)WSLAB);
        bulk_g2s(sb + SM_W, g_Wr + (size_t)(dir * 64 + blk) * WSLAB, (uint32_t)WSLAB, mb0 + 32);
    }
    __syncthreads();
    mbar_wait(mb0 + 32, 0);

    const uint32_t aRow  = (uint32_t)(wm + (lane & 15));
    const uint32_t aByte = (lane & 16) ? 16u : 0u;
    const uint32_t bRow  = (uint32_t)(wn + (lane & 7) + ((lane & 16) ? 8 : 0));
    const uint32_t bByte = (lane & 8) ? 16u : 0u;

    const float* xprjD = g_xproj + (size_t)dir * MM * FOURH;
    unsigned* bar = &g_gbar[dir];
    const char* hbase = g_hA + (size_t)dir * 2 * HA_SZ;

    // cell identity for this thread
    const int r0    = wm + (lane >> 2);                       // fragment row (batch)
    const int colp  = wn + (lane & 3) * 2;                    // fragment col base (ni adds 8)
    const int b_cell = r0 + ((lane & 1) << 3);                // cell batch
    const int hhA   = (wn >> 2) + ((lane >> 1) & 1);          // hh for ni=0
    const int chunk = blk >> 4;
    const uint32_t klocByte = (uint32_t)((blk & 15) * 16);
    float cst[2] = {0.f, 0.f};

    for (int t = 0; t < TT; t++) {
        const int tt = dir ? (TT - 1 - t) : t;

        if (tid == 0) {
            asm volatile("fence.proxy.async.shared::cta;" ::: "memory");
            const char* src = hbase + (size_t)(t & 1) * HA_SZ;
#pragma unroll
            for (int c = 0; c < 4; c++) {
                mbar_expect_tx(mb0 + c * 8, (uint32_t)CH_SZ);
                bulk_g2s(sb + SM_A + c * CH_SZ, src + c * CH_SZ, (uint32_t)CH_SZ, mb0 + c * 8);
            }
        }

        // Prefetch xproj fragment addends + mask
        float2 xg[2][2];
        {
            const float* base = xprjD + (size_t)tt * BB * FOURH + blk * 32;
#pragma unroll
            for (int ni = 0; ni < 2; ni++) {
                xg[ni][0] = *(const float2*)&base[(size_t)r0 * FOURH + colp + ni * 8];
                xg[ni][1] = *(const float2*)&base[(size_t)(r0 + 8) * FOURH + colp + ni * 8];
            }
        }
        const float mreg = (float)mask[b_cell * TT + tt];

        // MMA: C[64b x 32pr] = h[64x512] . Wslice^T (split bf16)
        float cf[2][4];
#pragma unroll
        for (int ni = 0; ni < 2; ni++)
#pragma unroll
            for (int j = 0; j < 4; j++) cf[ni][j] = 0.f;

        const uint32_t par = (uint32_t)(t & 1);
#pragma unroll
        for (int c = 0; c < 4; c++) {
            mbar_wait(mb0 + c * 8, par);
            uint32_t baseA = sb + SM_A + (uint32_t)c * CH_SZ;
#pragma unroll
            for (int ks = 0; ks < 8; ks++) {
                uint32_t ah[4], al[4], bh[4], bl[4];
                uint32_t ra = aRow * 272 + (uint32_t)ks * 32 + aByte;
                ldm_x4(ah[0], ah[1], ah[2], ah[3], baseA + ra);
                ldm_x4(al[0], al[1], al[2], al[3], baseA + CH_HALF + ra);
                uint32_t kb = ((uint32_t)(c * 8 + ks)) * 32 + bByte;
                uint32_t rb = sb + SM_W + bRow * 1040 + kb;
                ldm_x4(bh[0], bh[1], bh[2], bh[3], rb);
                ldm_x4(bl[0], bl[1], bl[2], bl[3], rb + WLO);
#pragma unroll
                for (int ni = 0; ni < 2; ni++) {
                    int o = ni * 2;
                    MMA_BF16(cf[ni], ah, bh[o], bh[o + 1]);
                    MMA_BF16(cf[ni], ah, bl[o], bl[o + 1]);
                    MMA_BF16(cf[ni], al, bh[o], bh[o + 1]);
                }
            }
        }

        // Cells directly from fragments: add xproj, shfl gate pairs, compute.
#pragma unroll
        for (int ni = 0; ni < 2; ni++) {
            cf[ni][0] += xg[ni][0].x;  cf[ni][1] += xg[ni][0].y;
            cf[ni][2] += xg[ni][1].x;  cf[ni][3] += xg[ni][1].y;

            float sx = (lane & 1) ? cf[ni][0] : cf[ni][2];
            float sy = (lane & 1) ? cf[ni][1] : cf[ni][3];
            float rx = __shfl_xor_sync(0xffffffffu, sx, 1);
            float ry = __shfl_xor_sync(0xffffffffu, sy, 1);

            float gi, gf, gg, go;
            if (!(lane & 1)) { gi = cf[ni][0]; gf = cf[ni][1]; gg = rx; go = ry; }
            else             { gi = rx;        gf = ry;        gg = cf[ni][2]; go = cf[ni][3]; }

            float si = sig_(gi);
            float sf = sig_(gf);
            float so = sig_(go);
            float tg = 2.f * sig_(2.f * gg) - 1.f;
            float c2 = sf * cst[ni] + si * tg;
            float tc = 2.f * sig_(2.f * c2) - 1.f;
            float hn = so * tc * mreg;
            cst[ni] = c2 * mreg;

            int hh = hhA + ni * 2;
            __nv_bfloat16 hb = __float2bfloat16(hn);
            __nv_bfloat16 lb = __float2bfloat16(hn - __bfloat162float(hb));
            sHhi[b_cell * 8 + hh] = __bfloat16_as_ushort(hb);
            sHlo[b_cell * 8 + hh] = __bfloat16_as_ushort(lb);
            if (mode) sF32[b_cell * 8 + hh] = hn;
        }
        __syncthreads();

        // Coalesced h stores (critical path)
        char* hout = (char*)(hbase + (size_t)((t + 1) & 1) * HA_SZ + (size_t)chunk * CH_SZ);
        if (tid < 64) {
            uint4 v = *(uint4*)((char*)sHhi + tid * 16);
            *(uint4*)(hout + tid * 272 + klocByte) = v;
        } else if (tid < 128) {
            int r = tid - 64;
            uint4 v = *(uint4*)((char*)sHlo + r * 16);
            *(uint4*)(hout + CH_HALF + r * 272 + klocByte) = v;
        }

        __threadfence();
        __syncthreads();
        if (tid == 0) atomicAdd(bar, 1u);

        // Off-critical-path stores overlap the barrier wait
        if (mode == 0) {
            if (tid >= 128 && tid < 192) {
                int r = tid - 128;
                uint4 v = *(uint4*)((char*)sHhi + r * 16);
                *(uint4*)((char*)g_Ahi + ((size_t)(tt * 64 + r) * 1024 + dir * 512 + blk * 8) * 2) = v;
            } else if (tid >= 192) {
                int r = tid - 192;
                uint4 v = *(uint4*)((char*)sHlo + r * 16);
                *(uint4*)((char*)g_Alo + ((size_t)(tt * 64 + r) * 1024 + dir * 512 + blk * 8) * 2) = v;
            }
        } else if (tid >= 128) {
            int r = (tid - 128) >> 1, half = tid & 1;
            float4 v = *(float4*)((char*)sF32 + r * 32 + half * 16);
            *(float4*)&outp[((size_t)tt * 64 + r) * 1024 + dir * 512 + blk * 8 + half * 4] = v;
        }

        if (tid == 0) {
            unsigned target = (unsigned)(t + 1) * 64u;
            unsigned v;
            do {
                asm volatile("ld.acquire.gpu.u32 %0, [%1];" : "=r"(v) : "l"(bar) : "memory");
            } while (v < target);
        }
        __syncthreads();
    }
}

// ---------------------------------------------------------------------------
// kernel_launch
// ---------------------------------------------------------------------------
extern "C" void kernel_launch(void* const* d_in, const int* in_sizes, int n_in,
                              void* d_out, int out_size)
{
    const float* x    = (const float*)d_in[0];
    const int*   mask = (const int*)  d_in[1];
    const float* w_ih = (const float*)d_in[2];
    const float* w_hh = (const float*)d_in[3];
    const float* b_ih = (const float*)d_in[4];
    const float* b_hh = (const float*)d_in[5];
    float* out = (float*)d_out;

    __nv_bfloat16 *pAh, *pAl, *pWh, *pWl;
    cudaGetSymbolAddress((void**)&pAh, g_Ahi);
    cudaGetSymbolAddress((void**)&pAl, g_Alo);
    cudaGetSymbolAddress((void**)&pWh, g_Whi);
    cudaGetSymbolAddress((void**)&pWl, g_Wlo);

    cudaFuncSetAttribute(lstm_mma,
                         cudaFuncAttributeMaxDynamicSharedMemorySize, SMEM_LSTM);
    cudaFuncSetAttribute(proj_mma,
                         cudaFuncAttributeMaxDynamicSharedMemorySize, SMEM_PROJ);

    dim3 gproj(128, 32);
    dim3 gpers(64, 2);

    for (int layer = 0; layer < 2; layer++) {
        if (layer == 0) pack_bf16<<<8192, 256>>>(x, pAh, pAl);

        pack_bf16<<<2048, 256>>>(w_ih + (size_t)layer * 2 * FOURH * KP, pWh, pWl);
        pack_Wr<<<128, 256>>>(w_hh + (size_t)layer * 2 * FOURH * HH);
        zero_state<<<136, 256>>>();

        proj_mma<<<gproj, 256, SMEM_PROJ>>>(
            pAh, pAl, pWh, pWl,
            b_ih + (size_t)layer * 2 * FOURH,
            b_hh + (size_t)layer * 2 * FOURH);

        lstm_mma<<<gpers, 256, SMEM_LSTM>>>(mask, (layer == 1) ? out : nullptr, layer);
    }
}

// round 9
// speedup vs baseline: 3.9031x; 1.0072x over previous
#include <cuda_runtime.h>
#include <cuda_bf16.h>
#include <math.h>
#include <stdint.h>

// Problem constants
#define TT     256
#define BB     64
#define HH     512
#define FOURH  2048
#define KP     1024
#define MM     (TT*BB)     // 16384

// ---------------------------------------------------------------------------
// Device scratch (static only)
// ---------------------------------------------------------------------------
__device__ float g_xproj[(size_t)2*MM*FOURH];        // input projections, pr-packed cols
__device__ unsigned g_cnt[2][4];                     // per (dir, chunk) producer counters

// proj operands: bf16 split, row-major. Layer-1 A is written by lstm_mma.
__device__ __align__(16) __nv_bfloat16 g_Ahi[(size_t)MM*KP];
__device__ __align__(16) __nv_bfloat16 g_Alo[(size_t)MM*KP];
__device__ __align__(16) __nv_bfloat16 g_Whi[(size_t)4096*KP];
__device__ __align__(16) __nv_bfloat16 g_Wlo[(size_t)4096*KP];

// recurrence W_hh: per (dir, block) slab: hi[32][1040B] + lo[32][1040B]
#define WSLAB 66560
#define WLO   33280
__device__ __align__(128) char g_Wr[(size_t)2*64*WSLAB];

// recurrence h state: [dir][ping][chunk4]{ hi[64][272B], lo[64][272B] }
#define CH_HALF 17408
#define CH_SZ   34816
#define HA_SZ   (4*CH_SZ)    // 139264 per (dir,ping)
__device__ __align__(128) char g_hA[(size_t)2*2*HA_SZ];

// ---------------------------------------------------------------------------
// PTX helpers
// ---------------------------------------------------------------------------
__device__ __forceinline__ uint32_t smem_u32(const void* p) {
    uint32_t a;
    asm("{ .reg .u64 t; cvta.to.shared.u64 t, %1; cvt.u32.u64 %0, t; }" : "=r"(a) : "l"(p));
    return a;
}
__device__ __forceinline__ void mbar_init(uint32_t mb, uint32_t cnt) {
    asm volatile("mbarrier.init.shared.b64 [%0], %1;" :: "r"(mb), "r"(cnt) : "memory");
}
__device__ __forceinline__ void mbar_expect_tx(uint32_t mb, uint32_t bytes) {
    asm volatile("mbarrier.arrive.expect_tx.shared.b64 _, [%0], %1;" :: "r"(mb), "r"(bytes) : "memory");
}
__device__ __forceinline__ void bulk_g2s(uint32_t dst, const void* src, uint32_t bytes, uint32_t mb) {
    asm volatile("cp.async.bulk.shared::cta.global.mbarrier::complete_tx::bytes [%0], [%1], %2, [%3];"
                 :: "r"(dst), "l"(src), "r"(bytes), "r"(mb) : "memory");
}
__device__ __forceinline__ void mbar_wait(uint32_t mb, uint32_t parity) {
    uint32_t done;
    asm volatile("{\n\t.reg .pred p;\n\t"
        "mbarrier.try_wait.parity.acquire.cta.shared::cta.b64 p, [%1], %2;\n\t"
        "selp.b32 %0, 1, 0, p;\n\t}"
        : "=r"(done) : "r"(mb), "r"(parity) : "memory");
    while (!done) {
        asm volatile("{\n\t.reg .pred p;\n\t"
            "mbarrier.try_wait.parity.acquire.cta.shared::cta.b64 p, [%1], %2, 0x989680;\n\t"
            "selp.b32 %0, 1, 0, p;\n\t}"
            : "=r"(done) : "r"(mb), "r"(parity) : "memory");
    }
}
__device__ __forceinline__ void cpa16(uint32_t dst, const void* src) {
    asm volatile("cp.async.cg.shared.global [%0], [%1], 16;" :: "r"(dst), "l"(src) : "memory");
}
__device__ __forceinline__ void ldm_x4(uint32_t& r0, uint32_t& r1, uint32_t& r2, uint32_t& r3,
                                       uint32_t addr) {
    asm volatile("ldmatrix.sync.aligned.m8n8.x4.shared.b16 {%0,%1,%2,%3}, [%4];"
                 : "=r"(r0), "=r"(r1), "=r"(r2), "=r"(r3) : "r"(addr));
}
#define MMA_BF16(c, a, b0v, b1v) \
    asm volatile("mma.sync.aligned.m16n8k16.row.col.f32.bf16.bf16.f32 " \
        "{%0,%1,%2,%3}, {%4,%5,%6,%7}, {%8,%9}, {%0,%1,%2,%3};" \
        : "+f"((c)[0]), "+f"((c)[1]), "+f"((c)[2]), "+f"((c)[3]) \
        : "r"((a)[0]), "r"((a)[1]), "r"((a)[2]), "r"((a)[3]), "r"(b0v), "r"(b1v))

__device__ __forceinline__ float sig_(float x) {
    return __fdividef(1.f, 1.f + __expf(-x));
}
__device__ __forceinline__ uint32_t pack_hilo(float a, float b, uint32_t& lo) {
    __nv_bfloat16 h0 = __float2bfloat16(a);
    __nv_bfloat16 h1 = __float2bfloat16(b);
    __nv_bfloat16 l0 = __float2bfloat16(a - __bfloat162float(h0));
    __nv_bfloat16 l1 = __float2bfloat16(b - __bfloat162float(h1));
    lo = (uint32_t)__bfloat16_as_ushort(l0) | ((uint32_t)__bfloat16_as_ushort(l1) << 16);
    return (uint32_t)__bfloat16_as_ushort(h0) | ((uint32_t)__bfloat16_as_ushort(h1) << 16);
}

// ---------------------------------------------------------------------------
// Zero h slot 0 (both dirs) + producer counters
// ---------------------------------------------------------------------------
__global__ void zero_state() {
    uint32_t i = blockIdx.x * 256 + threadIdx.x;
    float* p = (float*)g_hA;
    if (i < HA_SZ / 4) {
        p[i] = 0.f;
        p[i + (2 * HA_SZ) / 4] = 0.f;
    }
    if (i < 8) ((unsigned*)g_cnt)[i] = 0u;
}

// ---------------------------------------------------------------------------
// Pack fp32 -> hi/lo bf16 (row-major, 8 elems/thread)
// ---------------------------------------------------------------------------
__global__ __launch_bounds__(256) void pack_bf16(
    const float* __restrict__ src,
    __nv_bfloat16* __restrict__ hi, __nv_bfloat16* __restrict__ lo)
{
    size_t i = ((size_t)blockIdx.x * 256 + threadIdx.x) * 8;
    float4 v0 = *(const float4*)(src + i);
    float4 v1 = *(const float4*)(src + i + 4);
    float xv[8] = {v0.x, v0.y, v0.z, v0.w, v1.x, v1.y, v1.z, v1.w};
    uint32_t hp[4], lp[4];
#pragma unroll
    for (int e = 0; e < 4; e++) hp[e] = pack_hilo(xv[2*e], xv[2*e+1], lp[e]);
    *(uint4*)(hi + i) = make_uint4(hp[0], hp[1], hp[2], hp[3]);
    *(uint4*)(lo + i) = make_uint4(lp[0], lp[1], lp[2], lp[3]);
}

// ---------------------------------------------------------------------------
// Pack W_hh into per-block slabs: row pr=hh*4+g  <-  W[g*512 + blk*8+hh][k]
// ---------------------------------------------------------------------------
__global__ __launch_bounds__(256) void pack_Wr(const float* __restrict__ whh) {
    const int dir = blockIdx.x >> 6, blk = blockIdx.x & 63;
    char* slab = g_Wr + (size_t)(dir * 64 + blk) * WSLAB;
    for (int i = threadIdx.x; i < 8192; i += 256) {
        int r = i >> 8;
        int k2 = (i & 255) * 2;
        int hh = r >> 2, g = r & 3;
        int grow = g * HH + blk * 8 + hh;
        float2 v = *(const float2*)&whh[((size_t)dir * FOURH + grow) * HH + k2];
        uint32_t lo, hi = pack_hilo(v.x, v.y, lo);
        *(uint32_t*)(slab + r * 1040 + k2 * 2) = hi;
        *(uint32_t*)(slab + WLO + r * 1040 + k2 * 2) = lo;
    }
}

// ---------------------------------------------------------------------------
// HMMA projection GEMM, 3-stage pipeline, CTA tile = 128 rows x 128 PR-cols.
// pr = hh*4+g; W natural row for pr: n = (pr&3)*512 + (pr>>2).
// ---------------------------------------------------------------------------
#define ROWB   144
#define TILEB  (128*ROWB)
#define STGB   (4*TILEB)                  // 73728
#define OFF_BIAS (3*STGB)                 // 221184
#define SMEM_PROJ (OFF_BIAS + 768)

__global__ __launch_bounds__(256, 1) void proj_mma(
    const __nv_bfloat16* __restrict__ Ah, const __nv_bfloat16* __restrict__ Al,
    const __nv_bfloat16* __restrict__ Wh, const __nv_bfloat16* __restrict__ Wl,
    const float* __restrict__ b1, const float* __restrict__ b2)
{
    extern __shared__ __align__(128) char smp[];
    const uint32_t sb = smem_u32(smp);
    float* bias = (float*)(smp + OFF_BIAS);

    const int tid  = threadIdx.x;
    const int lane = tid & 31;
    const int w    = tid >> 5;
    const int m0   = blockIdx.x * 128;
    const int dir  = blockIdx.y >> 4;
    const int prG  = (blockIdx.y & 15) * 128;
    const int prB  = prG >> 2;
    const int wm   = (w >> 2) * 64;
    const int wn   = (w & 3) * 32;

    if (tid < 128) {
        int n = (tid & 3) * 512 + prB + (tid >> 2);
        bias[tid] = b1[dir * FOURH + n] + b2[dir * FOURH + n];
    }

    int cr[16], cc[16], ct[16];
#pragma unroll
    for (int i = 0; i < 16; i++) {
        int c = i * 256 + tid;
        ct[i] = c >> 10; cr[i] = (c >> 3) & 127; cc[i] = c & 7;
    }

    auto load_stage = [&](int s, int kt) {
        uint32_t base = sb + (uint32_t)s * STGB;
#pragma unroll
        for (int i = 0; i < 16; i++) {
            uint32_t dst = base + (uint32_t)ct[i] * TILEB + (uint32_t)cr[i] * ROWB + (uint32_t)cc[i] * 16;
            const __nv_bfloat16* g;
            if (ct[i] == 0)      g = Ah + (size_t)(m0 + cr[i]) * KP + kt * 64 + cc[i] * 8;
            else if (ct[i] == 1) g = Al + (size_t)(m0 + cr[i]) * KP + kt * 64 + cc[i] * 8;
            else {
                int n = (cr[i] & 3) * 512 + prB + (cr[i] >> 2);
                const __nv_bfloat16* Wb = (ct[i] == 2) ? Wh : Wl;
                g = Wb + (size_t)(dir * FOURH + n) * KP + kt * 64 + cc[i] * 8;
            }
            cpa16(dst, g);
        }
        asm volatile("cp.async.commit_group;" ::: "memory");
    };

    float c[4][4][4];
#pragma unroll
    for (int mi = 0; mi < 4; mi++)
#pragma unroll
        for (int ni = 0; ni < 4; ni++)
#pragma unroll
            for (int j = 0; j < 4; j++) c[mi][ni][j] = 0.f;

    const uint32_t aRow  = (uint32_t)(wm + (lane & 15));
    const uint32_t aByte = (lane & 16) ? 16u : 0u;
    const uint32_t bRow  = (uint32_t)(wn + (lane & 7) + ((lane & 16) ? 8 : 0));
    const uint32_t bByte = (lane & 8) ? 16u : 0u;

    load_stage(0, 0);
    load_stage(1, 1);

    for (int kt = 0; kt < 16; kt++) {
        if (kt + 2 < 16) {
            load_stage((kt + 2) % 3, kt + 2);
            asm volatile("cp.async.wait_group 2;" ::: "memory");
        } else if (kt + 1 < 16) {
            asm volatile("cp.async.wait_group 1;" ::: "memory");
        } else {
            asm volatile("cp.async.wait_group 0;" ::: "memory");
        }
        __syncthreads();

        uint32_t st = sb + (uint32_t)(kt % 3) * STGB;
#pragma unroll
        for (int ks = 0; ks < 4; ks++) {
            uint32_t kb = (uint32_t)(ks * 32);
            uint32_t ah[4][4], al[4][4], bh[2][4], bl[2][4];
#pragma unroll
            for (int mi = 0; mi < 4; mi++) {
                uint32_t ra = (aRow + mi * 16) * ROWB + kb + aByte;
                ldm_x4(ah[mi][0], ah[mi][1], ah[mi][2], ah[mi][3], st + ra);
                ldm_x4(al[mi][0], al[mi][1], al[mi][2], al[mi][3], st + TILEB + ra);
            }
#pragma unroll
            for (int np = 0; np < 2; np++) {
                uint32_t rb = (bRow + np * 16) * ROWB + kb + bByte;
                ldm_x4(bh[np][0], bh[np][1], bh[np][2], bh[np][3], st + 2 * TILEB + rb);
                ldm_x4(bl[np][0], bl[np][1], bl[np][2], bl[np][3], st + 3 * TILEB + rb);
            }
#pragma unroll
            for (int mi = 0; mi < 4; mi++)
#pragma unroll
                for (int ni = 0; ni < 4; ni++) {
                    int np = ni >> 1, o = (ni & 1) * 2;
                    MMA_BF16(c[mi][ni], ah[mi], bh[np][o], bh[np][o + 1]);
                    MMA_BF16(c[mi][ni], ah[mi], bl[np][o], bl[np][o + 1]);
                    MMA_BF16(c[mi][ni], al[mi], bh[np][o], bh[np][o + 1]);
                }
        }
        __syncthreads();
    }

    float* outD = g_xproj + (size_t)dir * MM * FOURH;
#pragma unroll
    for (int mi = 0; mi < 4; mi++) {
        int row0 = m0 + wm + mi * 16 + (lane >> 2);
#pragma unroll
        for (int ni = 0; ni < 4; ni++) {
            int colL = wn + ni * 8 + (lane & 3) * 2;
            float bx = bias[colL], by = bias[colL + 1];
            *(float2*)&outD[(size_t)row0 * FOURH + prG + colL] =
                make_float2(c[mi][ni][0] + bx, c[mi][ni][1] + by);
            *(float2*)&outD[(size_t)(row0 + 8) * FOURH + prG + colL] =
                make_float2(c[mi][ni][2] + bx, c[mi][ni][3] + by);
        }
    }
}

// ---------------------------------------------------------------------------
// Persistent HMMA recurrence with per-chunk producer counters.
// grid = (64 blk, 2 dir), 256 threads (8 warps). 2 syncthreads per step.
// Warp c (c<4) lane 0 spins on cnt[dir][c] then issues chunk-c bulk copy.
// Publish: one syncthreads + tid0 red.release.gpu (replaces threadfence-all).
// ---------------------------------------------------------------------------
#define SM_A  0                         // 4 chunks x (hi 17408 + lo 17408)
#define SM_W  139264                    // hi[32][1040] + lo[32][1040]
#define SM_ST 205824                    // staging: hi 1KB | lo 1KB | f32 2KB
#define SM_MB 209920                    // 5 mbarriers
#define SMEM_LSTM 209984

__global__ __launch_bounds__(256, 1) void lstm_mma(
    const int* __restrict__ mask,     // [B][T]
    float*     __restrict__ outp,     // [T][B][2H] (mode 1)
    int mode)
{
    extern __shared__ __align__(128) char sm[];
    const uint32_t sb = smem_u32(sm);
    uint16_t* sHhi = (uint16_t*)(sm + SM_ST);
    uint16_t* sHlo = (uint16_t*)(sm + SM_ST + 1024);
    float*    sF32 = (float*)(sm + SM_ST + 2048);

    const int dir = blockIdx.y;
    const int blk = blockIdx.x;
    const int tid = threadIdx.x;
    const int lane = tid & 31;
    const int w = tid >> 5;
    const int wm = (w >> 1) * 16;       // batch offset
    const int wn = (w & 1) * 16;        // pr offset

    const uint32_t mb0 = sb + SM_MB;
    if (tid == 0) {
        for (int c = 0; c < 5; c++) mbar_init(mb0 + c * 8, 1);
        asm volatile("fence.proxy.async.shared::cta;" ::: "memory");
        mbar_expect_tx(mb0 + 32, (uint32_t)WSLAB);
        bulk_g2s(sb + SM_W, g_Wr + (size_t)(dir * 64 + blk) * WSLAB, (uint32_t)WSLAB, mb0 + 32);
    }
    __syncthreads();
    mbar_wait(mb0 + 32, 0);

    const uint32_t aRow  = (uint32_t)(wm + (lane & 15));
    const uint32_t aByte = (lane & 16) ? 16u : 0u;
    const uint32_t bRow  = (uint32_t)(wn + (lane & 7) + ((lane & 16) ? 8 : 0));
    const uint32_t bByte = (lane & 8) ? 16u : 0u;

    const float* xprjD = g_xproj + (size_t)dir * MM * FOURH;
    const char* hbase = g_hA + (size_t)dir * 2 * HA_SZ;
    unsigned* mycnt = &g_cnt[dir][blk >> 4];      // counter this block increments
    unsigned* spincnt = &g_cnt[dir][w & 3];       // counter warp w (<4) spins on

    // cell identity for this thread
    const int r0    = wm + (lane >> 2);
    const int colp  = wn + (lane & 3) * 2;
    const int b_cell = r0 + ((lane & 1) << 3);
    const int hhA   = (wn >> 2) + ((lane >> 1) & 1);
    const int chunk = blk >> 4;
    const uint32_t klocByte = (uint32_t)((blk & 15) * 16);
    float cst[2] = {0.f, 0.f};

    for (int t = 0; t < TT; t++) {
        const int tt = dir ? (TT - 1 - t) : t;

        // Per-chunk acquire + copy: warp c lane 0 handles chunk c
        if (w < 4 && lane == 0) {
            unsigned target = 16u * (unsigned)t;
            unsigned v;
            do {
                asm volatile("ld.acquire.gpu.u32 %0, [%1];" : "=r"(v) : "l"(spincnt) : "memory");
            } while (v < target);
            asm volatile("fence.proxy.async.shared::cta;" ::: "memory");
            const char* src = hbase + (size_t)(t & 1) * HA_SZ + (size_t)w * CH_SZ;
            mbar_expect_tx(mb0 + w * 8, (uint32_t)CH_SZ);
            bulk_g2s(sb + SM_A + (uint32_t)w * CH_SZ, src, (uint32_t)CH_SZ, mb0 + w * 8);
        }

        // Prefetch xproj fragment addends + mask (LDGs fly during copies)
        float2 xg[2][2];
        {
            const float* base = xprjD + (size_t)tt * BB * FOURH + blk * 32;
#pragma unroll
            for (int ni = 0; ni < 2; ni++) {
                xg[ni][0] = *(const float2*)&base[(size_t)r0 * FOURH + colp + ni * 8];
                xg[ni][1] = *(const float2*)&base[(size_t)(r0 + 8) * FOURH + colp + ni * 8];
            }
        }
        const float mreg = (float)mask[b_cell * TT + tt];

        // MMA: C[64b x 32pr] = h[64x512] . Wslice^T (split bf16)
        float cf[2][4];
#pragma unroll
        for (int ni = 0; ni < 2; ni++)
#pragma unroll
            for (int j = 0; j < 4; j++) cf[ni][j] = 0.f;

        const uint32_t par = (uint32_t)(t & 1);
#pragma unroll
        for (int c = 0; c < 4; c++) {
            mbar_wait(mb0 + c * 8, par);
            uint32_t baseA = sb + SM_A + (uint32_t)c * CH_SZ;
#pragma unroll
            for (int ks = 0; ks < 8; ks++) {
                uint32_t ah[4], al[4], bh[4], bl[4];
                uint32_t ra = aRow * 272 + (uint32_t)ks * 32 + aByte;
                ldm_x4(ah[0], ah[1], ah[2], ah[3], baseA + ra);
                ldm_x4(al[0], al[1], al[2], al[3], baseA + CH_HALF + ra);
                uint32_t kb = ((uint32_t)(c * 8 + ks)) * 32 + bByte;
                uint32_t rb = sb + SM_W + bRow * 1040 + kb;
                ldm_x4(bh[0], bh[1], bh[2], bh[3], rb);
                ldm_x4(bl[0], bl[1], bl[2], bl[3], rb + WLO);
#pragma unroll
                for (int ni = 0; ni < 2; ni++) {
                    int o = ni * 2;
                    MMA_BF16(cf[ni], ah, bh[o], bh[o + 1]);
                    MMA_BF16(cf[ni], ah, bl[o], bl[o + 1]);
                    MMA_BF16(cf[ni], al, bh[o], bh[o + 1]);
                }
            }
        }

        // Cells directly from fragments
#pragma unroll
        for (int ni = 0; ni < 2; ni++) {
            cf[ni][0] += xg[ni][0].x;  cf[ni][1] += xg[ni][0].y;
            cf[ni][2] += xg[ni][1].x;  cf[ni][3] += xg[ni][1].y;

            float sx = (lane & 1) ? cf[ni][0] : cf[ni][2];
            float sy = (lane & 1) ? cf[ni][1] : cf[ni][3];
            float rx = __shfl_xor_sync(0xffffffffu, sx, 1);
            float ry = __shfl_xor_sync(0xffffffffu, sy, 1);

            float gi, gf, gg, go;
            if (!(lane & 1)) { gi = cf[ni][0]; gf = cf[ni][1]; gg = rx; go = ry; }
            else             { gi = rx;        gf = ry;        gg = cf[ni][2]; go = cf[ni][3]; }

            float si = sig_(gi);
            float sf = sig_(gf);
            float so = sig_(go);
            float tg = 2.f * sig_(2.f * gg) - 1.f;
            float c2 = sf * cst[ni] + si * tg;
            float tc = 2.f * sig_(2.f * c2) - 1.f;
            float hn = so * tc * mreg;
            cst[ni] = c2 * mreg;

            int hh = hhA + ni * 2;
            __nv_bfloat16 hb = __float2bfloat16(hn);
            __nv_bfloat16 lb = __float2bfloat16(hn - __bfloat162float(hb));
            sHhi[b_cell * 8 + hh] = __bfloat16_as_ushort(hb);
            sHlo[b_cell * 8 + hh] = __bfloat16_as_ushort(lb);
            if (mode) sF32[b_cell * 8 + hh] = hn;
        }
        __syncthreads();   // sync1: cells staged

        // Stores: h state (tid<128), aux outputs (tid>=128)
        char* hout = (char*)(hbase + (size_t)((t + 1) & 1) * HA_SZ + (size_t)chunk * CH_SZ);
        if (tid < 64) {
            uint4 v = *(uint4*)((char*)sHhi + tid * 16);
            *(uint4*)(hout + tid * 272 + klocByte) = v;
        } else if (tid < 128) {
            int r = tid - 64;
            uint4 v = *(uint4*)((char*)sHlo + r * 16);
            *(uint4*)(hout + CH_HALF + r * 272 + klocByte) = v;
        } else if (mode == 0) {
            if (tid < 192) {
                int r = tid - 128;
                uint4 v = *(uint4*)((char*)sHhi + r * 16);
                *(uint4*)((char*)g_Ahi + ((size_t)(tt * 64 + r) * 1024 + dir * 512 + blk * 8) * 2) = v;
            } else {
                int r = tid - 192;
                uint4 v = *(uint4*)((char*)sHlo + r * 16);
                *(uint4*)((char*)g_Alo + ((size_t)(tt * 64 + r) * 1024 + dir * 512 + blk * 8) * 2) = v;
            }
        } else {
            int r = (tid - 128) >> 1, half = tid & 1;
            float4 v = *(float4*)((char*)sF32 + r * 32 + half * 16);
            *(float4*)&outp[((size_t)tt * 64 + r) * 1024 + dir * 512 + blk * 8 + half * 4] = v;
        }

        __syncthreads();   // sync2: all stores issued; also guards mbar re-arm
        if (tid == 0) {
            asm volatile("red.release.gpu.global.add.u32 [%0], %1;" :: "l"(mycnt), "r"(1u) : "memory");
        }
    }
}

// ---------------------------------------------------------------------------
// kernel_launch
// ---------------------------------------------------------------------------
extern "C" void kernel_launch(void* const* d_in, const int* in_sizes, int n_in,
                              void* d_out, int out_size)
{
    const float* x    = (const float*)d_in[0];
    const int*   mask = (const int*)  d_in[1];
    const float* w_ih = (const float*)d_in[2];
    const float* w_hh = (const float*)d_in[3];
    const float* b_ih = (const float*)d_in[4];
    const float* b_hh = (const float*)d_in[5];
    float* out = (float*)d_out;

    __nv_bfloat16 *pAh, *pAl, *pWh, *pWl;
    cudaGetSymbolAddress((void**)&pAh, g_Ahi);
    cudaGetSymbolAddress((void**)&pAl, g_Alo);
    cudaGetSymbolAddress((void**)&pWh, g_Whi);
    cudaGetSymbolAddress((void**)&pWl, g_Wlo);

    cudaFuncSetAttribute(lstm_mma,
                         cudaFuncAttributeMaxDynamicSharedMemorySize, SMEM_LSTM);
    cudaFuncSetAttribute(proj_mma,
                         cudaFuncAttributeMaxDynamicSharedMemorySize, SMEM_PROJ);

    dim3 gproj(128, 32);
    dim3 gpers(64, 2);

    for (int layer = 0; layer < 2; layer++) {
        if (layer == 0) pack_bf16<<<8192, 256>>>(x, pAh, pAl);

        pack_bf16<<<2048, 256>>>(w_ih + (size_t)layer * 2 * FOURH * KP, pWh, pWl);
        pack_Wr<<<128, 256>>>(w_hh + (size_t)layer * 2 * FOURH * HH);
        zero_state<<<136, 256>>>();

        proj_mma<<<gproj, 256, SMEM_PROJ>>>(
            pAh, pAl, pWh, pWl,
            b_ih + (size_t)layer * 2 * FOURH,
            b_hh + (size_t)layer * 2 * FOURH);

        lstm_mma<<<gpers, 256, SMEM_LSTM>>>(mask, (layer == 1) ? out : nullptr, layer);
    }
}